// round 13
// baseline (speedup 1.0000x reference)
#include <cuda_runtime.h>
#include <math.h>

#define BB 8
#define NN 1024
#define KK 20
#define HH 64
#define CD 128
#define CATC 256
#define CATSTR (CATC*3*NN)
#define NBLK 2048   // statsA partial blocks = (NN/4)*BB

typedef unsigned long long u64;

// ---------------- scratch ----------------
__device__ float  g_pts[BB*3*NN];
__device__ float  g_cat[BB*CATC*3*NN];
__device__ float  g_xx[BB*NN];
__device__ float  g_dist[BB*NN*NN];
__device__ int    g_idx[BB*NN*KK];
// h-contiguous layout: [b][n][h] float4
__device__ float4 g_yf[BB*NN*HH];
__device__ float4 g_qf[BB*NN*HH];
__device__ float4 g_yd[BB*NN*HH];
__device__ float4 g_qd[BB*NN*HH];
__device__ double g_p1[HH*NBLK], g_p2[HH*NBLK];   // partial Σnm, Σnm²
__device__ float  g_bnA[CD], g_bnB[CD];
__device__ float4 g_pf[BB*CD*NN];
__device__ float4 g_df[BB*NN];

__device__ __forceinline__ float warpSum(float v){
    #pragma unroll
    for(int o=16;o;o>>=1) v += __shfl_down_sync(0xffffffffu, v, o);
    return v;
}
__device__ __forceinline__ double warpSumD(double v){
    #pragma unroll
    for(int o=16;o;o>>=1) v += __shfl_down_sync(0xffffffffu, v, o);
    return v;
}

// packed f32x2 helpers (sm_103a)
__device__ __forceinline__ u64 ffma2(u64 a, u64 b, u64 c){
    u64 d;
    asm("fma.rn.f32x2 %0, %1, %2, %3;" : "=l"(d) : "l"(a), "l"(b), "l"(c));
    return d;
}
__device__ __forceinline__ u64 pack2(float x){
    u64 d;
    asm("mov.b64 %0, {%1, %1};" : "=l"(d) : "f"(x));
    return d;
}
__device__ __forceinline__ void unpack2(u64 d, float& lo, float& hi){
    asm("mov.b64 {%0, %1}, %2;" : "=f"(lo), "=f"(hi) : "l"(d));
}

// ---------------- 0: transpose x[B,N,3] -> pts[B,3,N] ----------------
__global__ void k_transpose(const float* __restrict__ x){
    int i = blockIdx.x*256 + threadIdx.x;
    if(i < BB*NN){
        int b = i>>10, n = i&1023;
        const float* src = x + (size_t)(b*NN+n)*3;
        g_pts[(b*3+0)*NN+n] = src[0];
        g_pts[(b*3+1)*NN+n] = src[1];
        g_pts[(b*3+2)*NN+n] = src[2];
    }
}

// ---------------- 1: squared norms per point ----------------
__global__ void k_xx(const float* __restrict__ in, int D, int bstr){
    int i = blockIdx.x*256 + threadIdx.x;
    int b = i>>10, n = i&1023;
    const float* fb = in + b*bstr;
    float s = 0.f;
    for(int d=0; d<D; d++){ float v = fb[d*NN+n]; s = fmaf(v,v,s); }
    g_xx[i] = s;
}

// ---------------- 2: neg pairwise distance (Gram), f32x2, FULL grid (R10 proven fastest) ----------------
__global__ void k_dist(const float* __restrict__ in, int D, int bstr){
    int b = blockIdx.z, n0 = blockIdx.y*64, m0 = blockIdx.x*64;
    __shared__ __align__(16) float sA[16][64];
    __shared__ __align__(16) float sB[16][64];
    int t = threadIdx.x;
    int r0 = (t>>4)<<2, c0 = (t&15)<<2;
    u64 acc2[4][2];
    #pragma unroll
    for(int ii=0;ii<4;ii++){ acc2[ii][0]=0ull; acc2[ii][1]=0ull; }
    const float* fb = in + b*bstr;
    for(int d0=0; d0<D; d0+=16){
        for(int l=t; l<1024; l+=256){
            int dd = l>>6, i = l&63, d = d0+dd;
            float va = (d<D) ? fb[d*NN + n0 + i] : 0.f;
            float vb = (d<D) ? fb[d*NN + m0 + i] : 0.f;
            sA[dd][i] = va; sB[dd][i] = vb;
        }
        __syncthreads();
        #pragma unroll
        for(int dd=0; dd<16; dd++){
            float4 av = *(const float4*)&sA[dd][r0];
            ulonglong2 bv = *(const ulonglong2*)&sB[dd][c0];
            u64 a0 = pack2(av.x), a1 = pack2(av.y), a2 = pack2(av.z), a3 = pack2(av.w);
            acc2[0][0] = ffma2(a0, bv.x, acc2[0][0]);
            acc2[0][1] = ffma2(a0, bv.y, acc2[0][1]);
            acc2[1][0] = ffma2(a1, bv.x, acc2[1][0]);
            acc2[1][1] = ffma2(a1, bv.y, acc2[1][1]);
            acc2[2][0] = ffma2(a2, bv.x, acc2[2][0]);
            acc2[2][1] = ffma2(a2, bv.y, acc2[2][1]);
            acc2[3][0] = ffma2(a3, bv.x, acc2[3][0]);
            acc2[3][1] = ffma2(a3, bv.y, acc2[3][1]);
        }
        __syncthreads();
    }
    float xn[4], xm[4];
    #pragma unroll
    for(int ii=0;ii<4;ii++) xn[ii] = g_xx[b*NN + n0 + r0 + ii];
    #pragma unroll
    for(int jj=0;jj<4;jj++) xm[jj] = g_xx[b*NN + m0 + c0 + jj];
    #pragma unroll
    for(int ii=0;ii<4;ii++){
        int n = n0 + r0 + ii;
        float a0,a1,a2,a3;
        unpack2(acc2[ii][0], a0, a1);
        unpack2(acc2[ii][1], a2, a3);
        float4 o;
        o.x = 2.f*a0 - xn[ii] - xm[0];
        o.y = 2.f*a1 - xn[ii] - xm[1];
        o.z = 2.f*a2 - xn[ii] - xm[2];
        o.w = 2.f*a3 - xn[ii] - xm[3];
        *(float4*)&g_dist[(size_t)(b*NN+n)*NN + m0 + c0] = o;
    }
}

// ---------------- 3: top-20 per row — warp per row, shfl argmax (frozen exact) ----------------
__global__ void k_topk(){
    int row = blockIdx.x*8 + (threadIdx.x>>5);
    int lane = threadIdx.x & 31;
    const float* dr = g_dist + (size_t)row*NN;
    float v[32];
    #pragma unroll
    for(int j=0;j<32;j++) v[j] = dr[lane + (j<<5)];   // coalesced
    float lv = v[0]; int li = 0;
    #pragma unroll
    for(int j=1;j<32;j++) if(v[j] > lv){ lv = v[j]; li = j; }
    int* outp = g_idx + row*KK;
    #pragma unroll 1
    for(int kk=0; kk<KK; kk++){
        float bv = lv; int bidx = lane + (li<<5);
        #pragma unroll
        for(int o=16;o;o>>=1){
            float ov = __shfl_xor_sync(0xffffffffu, bv, o);
            int   oi = __shfl_xor_sync(0xffffffffu, bidx, o);
            if(ov > bv || (ov == bv && oi < bidx)){ bv = ov; bidx = oi; }
        }
        if(lane == 0) outp[kk] = bidx;
        if((bidx & 31) == lane){
            v[bidx>>5] = -3.0e38f;
            lv = v[0]; li = 0;
            #pragma unroll
            for(int j=1;j<32;j++) if(v[j] > lv){ lv = v[j]; li = j; }
        }
    }
}

// ---------------- 4: tiny GEMMs y/q = W @ x (f32x2), output [b][n][h] float4 ----------------
// grid (N/32, tensor 0..3, B); block 192 = 64h x 3comp
__global__ void k_yq(const float* __restrict__ in, int C, int bstr,
                     const float* __restrict__ wf, const float* __restrict__ wd){
    int b = blockIdx.z, tensor = blockIdx.y, n0 = blockIdx.x*32;
    __shared__ __align__(16) float xs[HH*3*32];
    __shared__ float os[3][HH][33];
    int t = threadIdx.x;                  // 192
    const float* xb = in + b*bstr;
    int R = C*3;
    for(int l=t; l<R*32; l+=192){
        int row = l>>5, col = l&31;
        xs[l] = xb[row*NN + n0 + col];
    }
    __syncthreads();
    int h = t/3, comp = t - h*3;
    const float* w = (tensor < 2) ? wf : wd;
    int twoC = 2*C;
    u64 acc[16];
    #pragma unroll
    for(int j=0;j<16;j++) acc[j]=0ull;
    for(int c=0;c<C;c++){
        float wv = w[h*twoC + c];
        if(tensor & 1) wv = w[h*twoC + C + c] - wv;
        u64 w2 = pack2(wv);
        const u64* xr = (const u64*)(xs + (c*3 + comp)*32);
        #pragma unroll
        for(int j=0;j<16;j++) acc[j] = ffma2(w2, xr[j], acc[j]);
    }
    #pragma unroll
    for(int j=0;j<16;j++){
        float f0,f1;
        unpack2(acc[j], f0, f1);
        os[comp][h][2*j]   = f0;
        os[comp][h][2*j+1] = f1;
    }
    __syncthreads();
    float4* outp = ((tensor==0)?g_yf:(tensor==1)?g_qf:(tensor==2)?g_yd:g_qd)
                   + ((size_t)b*NN + n0)*HH;
    for(int idx=t; idx<HH*32; idx+=192){
        int n = idx>>6, h2 = idx&63;       // consecutive threads -> consecutive h
        outp[(size_t)n*HH + h2] = make_float4(os[0][h2][n], os[1][h2][n], os[2][h2][n], 0.f);
    }
}

// ---------------- 5: pass A — BN stats; coalesced h-gathers; nm-form double (2-chain ILP) ----------------
// grid (NN/4, BB), block 256: t = nloc*64 + h
__global__ void k_statsA(){
    int b = blockIdx.y, t = threadIdx.x;
    int h = t & 63, nloc = t >> 6;
    int n = blockIdx.x*4 + nloc;
    const float4* yf = g_yf + (size_t)b*NN*HH;
    float4 q = g_qf[((size_t)b*NN + n)*HH + h];
    const int* ix = g_idx + (b*NN + n)*KK;
    double s1a = 0.0, s2a = 0.0, s1b = 0.0, s2b = 0.0;
    #pragma unroll
    for(int k=0;k<KK;k+=2){
        int m0 = ix[k], m1 = ix[k+1];
        float4 y0 = yf[(size_t)m0*HH + h];
        float4 y1 = yf[(size_t)m1*HH + h];
        float px0 = y0.x+q.x, py0 = y0.y+q.y, pz0 = y0.z+q.z;
        float px1 = y1.x+q.x, py1 = y1.y+q.y, pz1 = y1.z+q.z;
        float ss0 = px0*px0 + py0*py0 + pz0*pz0;
        float ss1 = px1*px1 + py1*py1 + pz1*pz1;
        float nm0 = sqrtf(ss0) + 1e-6f;      // exact reference norm
        float nm1 = sqrtf(ss1) + 1e-6f;
        double nd0 = (double)nm0, nd1 = (double)nm1;
        s1a += nd0; s2a += nd0*nd0;          // nm-form (frozen; eps-algebra banned)
        s1b += nd1; s2b += nd1*nd1;
    }
    double s1 = s1a + s1b, s2 = s2a + s2b;
    __shared__ double sr[256], ssd[256];
    sr[t] = s1; ssd[t] = s2;
    __syncthreads();
    if(t < 64){
        double S1 = sr[t] + sr[t+64] + sr[t+128] + sr[t+192];
        double S2 = ssd[t] + ssd[t+64] + ssd[t+128] + ssd[t+192];
        int blk = b*(NN/4) + blockIdx.x;     // 0..NBLK-1
        g_p1[t*NBLK + blk] = S1;
        g_p2[t*NBLK + blk] = S2;
    }
}

// ---------------- 6: reduce partials -> folded BN coeffs (plain fp64) ----------------
__global__ void k_statsR(const float* __restrict__ bnw, const float* __restrict__ bnb){
    int h = blockIdx.x, t = threadIdx.x;   // 256 threads
    double s1=0.0, s2=0.0;
    for(int i=t; i<NBLK; i+=256){ s1 += g_p1[h*NBLK+i]; s2 += g_p2[h*NBLK+i]; }
    s1 = warpSumD(s1); s2 = warpSumD(s2);
    __shared__ double a1[8], a2[8];
    if((t&31)==0){ a1[t>>5]=s1; a2[t>>5]=s2; }
    __syncthreads();
    if(t==0){
        double S1=0.0, S2=0.0;
        #pragma unroll
        for(int u=0;u<8;u++){ S1+=a1[u]; S2+=a2[u]; }
        const double invc = 1.0/(double)(BB*NN*KK);
        double m = S1*invc;
        double var = S2*invc - m*m;
        double istd = 1.0/sqrt(var + 1e-5);
        float A = (float)(istd * (double)bnw[h]);
        g_bnA[h] = A;
        g_bnB[h] = (float)((double)bnb[h] - m*(double)A);
    }
}

// ---------------- 7: pass B — coalesced h-gathers; BN + dir-LeakyReLU + mean over k ----------------
// grid (NN/4, BB), block 256: t = nloc*64 + h
__global__ void k_passB(int c0){
    int b = blockIdx.y, t = threadIdx.x;
    int h = t & 63;
    int n = blockIdx.x*4 + (t >> 6);
    size_t base = (size_t)b*NN*HH;
    float4 q  = g_qf[base + (size_t)n*HH + h];
    float4 qd = g_qd[base + (size_t)n*HH + h];
    const int* ix = g_idx + (b*NN + n)*KK;
    float A = g_bnA[h], Bc = g_bnB[h];
    float ox=0.f, oy=0.f, oz=0.f;
    #pragma unroll 5
    for(int k=0;k<KK;k++){
        int m = ix[k];
        float4 y  = g_yf[base + (size_t)m*HH + h];
        float4 yD = g_yd[base + (size_t)m*HH + h];
        float px = y.x+q.x, py = y.y+q.y, pz = y.z+q.z;
        float dx = yD.x+qd.x, dy = yD.y+qd.y, dz = yD.z+qd.z;
        float ss = px*px + py*py + pz*pz;
        float nm = sqrtf(ss) + 1e-6f;
        float inv = __fdividef(1.f, nm);
        float sc = A + Bc*inv;
        px *= sc; py *= sc; pz *= sc;
        float dot = px*dx + py*dy + pz*dz;
        if(dot < 0.f){
            float cc = 0.8f*dot*__fdividef(1.f, dx*dx + dy*dy + dz*dz + 1e-6f);
            px -= cc*dx; py -= cc*dy; pz -= cc*dz;
        }
        ox += px; oy += py; oz += pz;
    }
    const float s = 1.f/(float)KK;
    int obase = b*CATSTR + (c0+h)*3*NN + n;
    g_cat[obase]        = ox*s;
    g_cat[obase+NN]     = oy*s;
    g_cat[obase+2*NN]   = oz*s;
}

// ---------------- 8: final p = wcf @ cat (f32x2) ----------------
__global__ void k_pgemm(const float* __restrict__ wcf){
    int b = blockIdx.z, h0 = blockIdx.y*64, col0 = blockIdx.x*64;
    __shared__ __align__(16) float sW[16][68];
    __shared__ __align__(16) float sX[16][64];
    int t = threadIdx.x;
    int r0 = (t>>4)<<2, c0 = (t&15)<<2;
    u64 acc2[4][2];
    #pragma unroll
    for(int ii=0;ii<4;ii++){ acc2[ii][0]=0ull; acc2[ii][1]=0ull; }
    const float* catb = g_cat + b*CATSTR;
    for(int cb=0; cb<CATC; cb+=16){
        for(int l=t; l<1024; l+=256){
            int i = l>>4, cc = l&15;
            sW[cc][i] = wcf[(h0+i)*CATC + cb + cc];
        }
        for(int l=t; l<1024; l+=256){
            int cc = l>>6, j = l&63;
            sX[cc][j] = catb[(cb+cc)*3072 + col0 + j];
        }
        __syncthreads();
        #pragma unroll
        for(int cc=0; cc<16; cc++){
            float4 av = *(const float4*)&sW[cc][r0];
            ulonglong2 bv = *(const ulonglong2*)&sX[cc][c0];
            u64 a0 = pack2(av.x), a1 = pack2(av.y), a2 = pack2(av.z), a3 = pack2(av.w);
            acc2[0][0] = ffma2(a0, bv.x, acc2[0][0]);
            acc2[0][1] = ffma2(a0, bv.y, acc2[0][1]);
            acc2[1][0] = ffma2(a1, bv.x, acc2[1][0]);
            acc2[1][1] = ffma2(a1, bv.y, acc2[1][1]);
            acc2[2][0] = ffma2(a2, bv.x, acc2[2][0]);
            acc2[2][1] = ffma2(a2, bv.y, acc2[2][1]);
            acc2[3][0] = ffma2(a3, bv.x, acc2[3][0]);
            acc2[3][1] = ffma2(a3, bv.y, acc2[3][1]);
        }
        __syncthreads();
    }
    float* pf = (float*)g_pf;
    #pragma unroll
    for(int ii=0;ii<4;ii++){
        int h = h0 + r0 + ii;
        float a0,a1,a2,a3;
        unpack2(acc2[ii][0], a0, a1);
        unpack2(acc2[ii][1], a2, a3);
        float vals[4] = {a0,a1,a2,a3};
        #pragma unroll
        for(int jj=0;jj<4;jj++){
            int col = col0 + c0 + jj;
            int n = col & 1023, comp = col >> 10;
            pf[(((b*CD)+h)*NN + n)*4 + comp] = vals[jj];
        }
    }
}

// ---------------- 9: final d = wcd @ cat ----------------
__global__ void k_dvec(const float* __restrict__ wcd){
    int i = blockIdx.x*256 + threadIdx.x;   // B*3072
    int b = i/3072, col = i - b*3072;
    const float* catb = g_cat + b*CATSTR;
    float s = 0.f;
    for(int c=0;c<CATC;c++) s = fmaf(wcd[c], catb[c*3072 + col], s);
    int n = col & 1023, comp = col >> 10;
    ((float*)g_df)[(b*NN+n)*4 + comp] = s;
}

// ---------------- 10: final BN stats (nm-form, double per element) ----------------
__global__ void k_fstats(const float* __restrict__ bw, const float* __restrict__ bb){
    int h = blockIdx.x, t = threadIdx.x;    // 256 threads
    double s1=0.0, s2=0.0;
    for(int i=t; i<BB*NN; i+=256){
        int b = i>>10, n = i&1023;
        float4 p = g_pf[((b*CD)+h)*NN + n];
        float ss = p.x*p.x + p.y*p.y + p.z*p.z;
        float nm = sqrtf(ss) + 1e-6f;
        double nd = (double)nm;
        s1 += nd; s2 += nd*nd;
    }
    __shared__ double sh1[8], sh2[8];
    s1 = warpSumD(s1); s2 = warpSumD(s2);
    if((t&31)==0){ sh1[t>>5]=s1; sh2[t>>5]=s2; }
    __syncthreads();
    if(t==0){
        double S1=0.0, S2=0.0;
        #pragma unroll
        for(int u=0;u<8;u++){ S1+=sh1[u]; S2+=sh2[u]; }
        const double invc = 1.0/(double)(BB*NN);
        double m = S1*invc;
        double var = S2*invc - m*m;
        double istd = 1.0/sqrt(var + 1e-5);
        float A = (float)(istd*(double)bw[h]);
        g_bnA[h] = A;
        g_bnB[h] = (float)((double)bb[h] - m*(double)A);
    }
}

// ---------------- 11: finalize — BN + leaky + mean over N ----------------
__global__ void k_final(float* __restrict__ out){
    int h = blockIdx.x, b = blockIdx.y;
    float A = g_bnA[h], Bc = g_bnB[h];
    float ox=0.f, oy=0.f, oz=0.f;
    for(int n=threadIdx.x; n<NN; n+=256){
        float4 p = g_pf[((b*CD)+h)*NN + n];
        float4 d = g_df[b*NN + n];
        float ss = p.x*p.x + p.y*p.y + p.z*p.z;
        float nm = sqrtf(ss) + 1e-6f;
        float r = __fdividef(1.f, nm);
        float sc = A + Bc*r;
        float px = p.x*sc, py = p.y*sc, pz = p.z*sc;
        float dot = px*d.x + py*d.y + pz*d.z;
        if(dot < 0.f){
            float cc = 0.8f*dot*__fdividef(1.f, d.x*d.x + d.y*d.y + d.z*d.z + 1e-6f);
            px -= cc*d.x; py -= cc*d.y; pz -= cc*d.z;
        }
        ox += px; oy += py; oz += pz;
    }
    __shared__ float sx[8], sy[8], sz[8];
    ox = warpSum(ox); oy = warpSum(oy); oz = warpSum(oz);
    int t = threadIdx.x;
    if((t&31)==0){ sx[t>>5]=ox; sy[t>>5]=oy; sz[t>>5]=oz; }
    __syncthreads();
    if(t==0){
        float X=0.f, Y=0.f, Z=0.f;
        #pragma unroll
        for(int u=0;u<8;u++){ X+=sx[u]; Y+=sy[u]; Z+=sz[u]; }
        const float s = 1.f/(float)NN;
        float* o = out + (b*CD + h)*3;
        o[0] = X*s; o[1] = Y*s; o[2] = Z*s;
    }
}

// ---------------- host orchestration ----------------
static void conv_layer(const float* in, int C, int bstr,
                       const float* wf, const float* wd,
                       const float* bnw, const float* bnb, int c0_out){
    int D = C*3;
    k_xx  <<<32, 256>>>(in, D, bstr);
    k_dist<<<dim3(16,16,BB), 256>>>(in, D, bstr);
    k_topk<<<BB*NN/8, 256>>>();
    k_yq  <<<dim3(NN/32, 4, BB), 192>>>(in, C, bstr, wf, wd);
    k_statsA<<<dim3(NN/4, BB), 256>>>();
    k_statsR<<<HH, 256>>>(bnw, bnb);
    k_passB<<<dim3(NN/4, BB), 256>>>(c0_out);
}

extern "C" void kernel_launch(void* const* d_in, const int* in_sizes, int n_in,
                              void* d_out, int out_size){
    const float* x    = (const float*)d_in[0];
    const float* w1f  = (const float*)d_in[1];
    const float* w1d  = (const float*)d_in[2];
    const float* bn1w = (const float*)d_in[3];
    const float* bn1b = (const float*)d_in[4];
    const float* w2f  = (const float*)d_in[5];
    const float* w2d  = (const float*)d_in[6];
    const float* bn2w = (const float*)d_in[7];
    const float* bn2b = (const float*)d_in[8];
    const float* w3f  = (const float*)d_in[9];
    const float* w3d  = (const float*)d_in[10];
    const float* bn3w = (const float*)d_in[11];
    const float* bn3b = (const float*)d_in[12];
    const float* w4f  = (const float*)d_in[13];
    const float* w4d  = (const float*)d_in[14];
    const float* bn4w = (const float*)d_in[15];
    const float* bn4b = (const float*)d_in[16];
    const float* wcf  = (const float*)d_in[17];
    const float* wcd  = (const float*)d_in[18];
    const float* bncw = (const float*)d_in[19];
    const float* bncb = (const float*)d_in[20];
    float* out = (float*)d_out;

    float *pts = nullptr, *cat = nullptr;
    cudaGetSymbolAddress((void**)&pts, g_pts);
    cudaGetSymbolAddress((void**)&cat, g_cat);

    k_transpose<<<32, 256>>>(x);

    conv_layer(pts, 1, 3*NN, w1f, w1d, bn1w, bn1b, 0);
    conv_layer(cat,            HH, CATSTR, w2f, w2d, bn2w, bn2b, HH);
    conv_layer(cat + HH*3*NN,  HH, CATSTR, w3f, w3d, bn3w, bn3b, 2*HH);
    conv_layer(cat + 2*HH*3*NN,HH, CATSTR, w4f, w4d, bn4w, bn4b, 3*HH);

    k_pgemm <<<dim3(3072/64, CD/64, BB), 256>>>(wcf);
    k_dvec  <<<BB*3072/256, 256>>>(wcd);
    k_fstats<<<CD, 256>>>(bncw, bncb);
    k_final <<<dim3(CD, BB), 256>>>(out);
}

// round 14
// speedup vs baseline: 1.0194x; 1.0194x over previous
#include <cuda_runtime.h>
#include <math.h>

#define BB 8
#define NN 1024
#define KK 20
#define HH 64
#define CD 128
#define CATC 256
#define CATSTR (CATC*3*NN)
#define NBLK 2048   // statsA partial blocks = (NN/4)*BB

typedef unsigned long long u64;

// ---------------- scratch ----------------
__device__ float  g_pts[BB*3*NN];
__device__ float  g_cat[BB*CATC*3*NN];
__device__ float  g_xx[BB*NN];
__device__ float  g_dist[BB*NN*NN];
__device__ int    g_idx[BB*NN*KK];
// h-contiguous layout: [b][n][h] float4
__device__ float4 g_yf[BB*NN*HH];
__device__ float4 g_qf[BB*NN*HH];
__device__ float4 g_yd[BB*NN*HH];
__device__ float4 g_qd[BB*NN*HH];
__device__ double g_p1[HH*NBLK], g_p2[HH*NBLK];   // partial Σnm, Σnm²
__device__ float  g_bnA[CD], g_bnB[CD];
__device__ float4 g_pf[BB*CD*NN];
__device__ float4 g_df[BB*NN];

__device__ __forceinline__ float warpSum(float v){
    #pragma unroll
    for(int o=16;o;o>>=1) v += __shfl_down_sync(0xffffffffu, v, o);
    return v;
}
__device__ __forceinline__ double warpSumD(double v){
    #pragma unroll
    for(int o=16;o;o>>=1) v += __shfl_down_sync(0xffffffffu, v, o);
    return v;
}

// packed f32x2 helpers (sm_103a)
__device__ __forceinline__ u64 ffma2(u64 a, u64 b, u64 c){
    u64 d;
    asm("fma.rn.f32x2 %0, %1, %2, %3;" : "=l"(d) : "l"(a), "l"(b), "l"(c));
    return d;
}
__device__ __forceinline__ u64 pack2(float x){
    u64 d;
    asm("mov.b64 %0, {%1, %1};" : "=l"(d) : "f"(x));
    return d;
}
__device__ __forceinline__ void unpack2(u64 d, float& lo, float& hi){
    asm("mov.b64 {%0, %1}, %2;" : "=f"(lo), "=f"(hi) : "l"(d));
}

// ---------------- 0: transpose x[B,N,3] -> pts[B,3,N] ----------------
__global__ void k_transpose(const float* __restrict__ x){
    int i = blockIdx.x*256 + threadIdx.x;
    if(i < BB*NN){
        int b = i>>10, n = i&1023;
        const float* src = x + (size_t)(b*NN+n)*3;
        g_pts[(b*3+0)*NN+n] = src[0];
        g_pts[(b*3+1)*NN+n] = src[1];
        g_pts[(b*3+2)*NN+n] = src[2];
    }
}

// ---------------- 1: squared norms per point ----------------
__global__ void k_xx(const float* __restrict__ in, int D, int bstr){
    int i = blockIdx.x*256 + threadIdx.x;
    int b = i>>10, n = i&1023;
    const float* fb = in + b*bstr;
    float s = 0.f;
    for(int d=0; d<D; d++){ float v = fb[d*NN+n]; s = fmaf(v,v,s); }
    g_xx[i] = s;
}

// ---------------- 2: neg pairwise distance (Gram), f32x2, FULL grid ----------------
__global__ void k_dist(const float* __restrict__ in, int D, int bstr){
    int b = blockIdx.z, n0 = blockIdx.y*64, m0 = blockIdx.x*64;
    __shared__ __align__(16) float sA[16][64];
    __shared__ __align__(16) float sB[16][64];
    int t = threadIdx.x;
    int r0 = (t>>4)<<2, c0 = (t&15)<<2;
    u64 acc2[4][2];
    #pragma unroll
    for(int ii=0;ii<4;ii++){ acc2[ii][0]=0ull; acc2[ii][1]=0ull; }
    const float* fb = in + b*bstr;
    for(int d0=0; d0<D; d0+=16){
        for(int l=t; l<1024; l+=256){
            int dd = l>>6, i = l&63, d = d0+dd;
            float va = (d<D) ? fb[d*NN + n0 + i] : 0.f;
            float vb = (d<D) ? fb[d*NN + m0 + i] : 0.f;
            sA[dd][i] = va; sB[dd][i] = vb;
        }
        __syncthreads();
        #pragma unroll
        for(int dd=0; dd<16; dd++){
            float4 av = *(const float4*)&sA[dd][r0];
            ulonglong2 bv = *(const ulonglong2*)&sB[dd][c0];
            u64 a0 = pack2(av.x), a1 = pack2(av.y), a2 = pack2(av.z), a3 = pack2(av.w);
            acc2[0][0] = ffma2(a0, bv.x, acc2[0][0]);
            acc2[0][1] = ffma2(a0, bv.y, acc2[0][1]);
            acc2[1][0] = ffma2(a1, bv.x, acc2[1][0]);
            acc2[1][1] = ffma2(a1, bv.y, acc2[1][1]);
            acc2[2][0] = ffma2(a2, bv.x, acc2[2][0]);
            acc2[2][1] = ffma2(a2, bv.y, acc2[2][1]);
            acc2[3][0] = ffma2(a3, bv.x, acc2[3][0]);
            acc2[3][1] = ffma2(a3, bv.y, acc2[3][1]);
        }
        __syncthreads();
    }
    float xn[4], xm[4];
    #pragma unroll
    for(int ii=0;ii<4;ii++) xn[ii] = g_xx[b*NN + n0 + r0 + ii];
    #pragma unroll
    for(int jj=0;jj<4;jj++) xm[jj] = g_xx[b*NN + m0 + c0 + jj];
    #pragma unroll
    for(int ii=0;ii<4;ii++){
        int n = n0 + r0 + ii;
        float a0,a1,a2,a3;
        unpack2(acc2[ii][0], a0, a1);
        unpack2(acc2[ii][1], a2, a3);
        float4 o;
        o.x = 2.f*a0 - xn[ii] - xm[0];
        o.y = 2.f*a1 - xn[ii] - xm[1];
        o.z = 2.f*a2 - xn[ii] - xm[2];
        o.w = 2.f*a3 - xn[ii] - xm[3];
        *(float4*)&g_dist[(size_t)(b*NN+n)*NN + m0 + c0] = o;
    }
}

// ---------------- 3: top-20 per row — warp per row, shfl argmax (frozen exact) ----------------
__global__ void k_topk(){
    int row = blockIdx.x*8 + (threadIdx.x>>5);
    int lane = threadIdx.x & 31;
    const float* dr = g_dist + (size_t)row*NN;
    float v[32];
    #pragma unroll
    for(int j=0;j<32;j++) v[j] = dr[lane + (j<<5)];   // coalesced
    float lv = v[0]; int li = 0;
    #pragma unroll
    for(int j=1;j<32;j++) if(v[j] > lv){ lv = v[j]; li = j; }
    int* outp = g_idx + row*KK;
    #pragma unroll 1
    for(int kk=0; kk<KK; kk++){
        float bv = lv; int bidx = lane + (li<<5);
        #pragma unroll
        for(int o=16;o;o>>=1){
            float ov = __shfl_xor_sync(0xffffffffu, bv, o);
            int   oi = __shfl_xor_sync(0xffffffffu, bidx, o);
            if(ov > bv || (ov == bv && oi < bidx)){ bv = ov; bidx = oi; }
        }
        if(lane == 0) outp[kk] = bidx;
        if((bidx & 31) == lane){
            v[bidx>>5] = -3.0e38f;
            lv = v[0]; li = 0;
            #pragma unroll
            for(int j=1;j<32;j++) if(v[j] > lv){ lv = v[j]; li = j; }
        }
    }
}

// ---------------- 4: tiny GEMMs y/q = W @ x (f32x2), PAIR-MERGED (xs loaded once) ----------------
// grid (N/32, pair 0..1, B); block 192 = 64h x 3comp
// pair 0 -> wf: yf (sub 0), qf (sub 1); pair 1 -> wd: yd, qd
__global__ void k_yq(const float* __restrict__ in, int C, int bstr,
                     const float* __restrict__ wf, const float* __restrict__ wd){
    int b = blockIdx.z, pair = blockIdx.y, n0 = blockIdx.x*32;
    __shared__ __align__(16) float xs[HH*3*32];
    __shared__ float os[3][HH][33];
    int t = threadIdx.x;                  // 192
    const float* xb = in + b*bstr;
    int R = C*3;
    for(int l=t; l<R*32; l+=192){
        int row = l>>5, col = l&31;
        xs[l] = xb[row*NN + n0 + col];
    }
    __syncthreads();
    int h = t/3, comp = t - h*3;
    const float* w = pair ? wd : wf;
    int twoC = 2*C;
    #pragma unroll 1
    for(int sub=0; sub<2; sub++){
        u64 acc[16];
        #pragma unroll
        for(int j=0;j<16;j++) acc[j]=0ull;
        for(int c=0;c<C;c++){
            float wv = w[h*twoC + c];
            if(sub) wv = w[h*twoC + C + c] - wv;
            u64 w2 = pack2(wv);
            const u64* xr = (const u64*)(xs + (c*3 + comp)*32);
            #pragma unroll
            for(int j=0;j<16;j++) acc[j] = ffma2(w2, xr[j], acc[j]);
        }
        #pragma unroll
        for(int j=0;j<16;j++){
            float f0,f1;
            unpack2(acc[j], f0, f1);
            os[comp][h][2*j]   = f0;
            os[comp][h][2*j+1] = f1;
        }
        __syncthreads();
        float4* outp = (pair==0 ? (sub==0 ? g_yf : g_qf)
                                : (sub==0 ? g_yd : g_qd))
                       + ((size_t)b*NN + n0)*HH;
        for(int idx=t; idx<HH*32; idx+=192){
            int n = idx>>6, h2 = idx&63;   // consecutive threads -> consecutive h
            outp[(size_t)n*HH + h2] = make_float4(os[0][h2][n], os[1][h2][n], os[2][h2][n], 0.f);
        }
        __syncthreads();
    }
}

// ---------------- 5: pass A — BN stats; coalesced h-gathers; nm-form double (straight chain) ----------------
// grid (NN/4, BB), block 256: t = nloc*64 + h
__global__ void k_statsA(){
    int b = blockIdx.y, t = threadIdx.x;
    int h = t & 63, nloc = t >> 6;
    int n = blockIdx.x*4 + nloc;
    const float4* yf = g_yf + (size_t)b*NN*HH;
    float4 q = g_qf[((size_t)b*NN + n)*HH + h];
    const int* ix = g_idx + (b*NN + n)*KK;
    double s1 = 0.0, s2 = 0.0;
    #pragma unroll
    for(int k=0;k<KK;k++){
        int m = ix[k];
        float4 y = yf[(size_t)m*HH + h];
        float px = y.x+q.x, py = y.y+q.y, pz = y.z+q.z;
        float ss = px*px + py*py + pz*pz;
        float nm = sqrtf(ss) + 1e-6f;        // exact reference norm
        double nd = (double)nm;
        s1 += nd; s2 += nd*nd;               // nm-form (frozen; eps-algebra banned)
    }
    __shared__ double sr[256], ssd[256];
    sr[t] = s1; ssd[t] = s2;
    __syncthreads();
    if(t < 64){
        double S1 = sr[t] + sr[t+64] + sr[t+128] + sr[t+192];
        double S2 = ssd[t] + ssd[t+64] + ssd[t+128] + ssd[t+192];
        int blk = b*(NN/4) + blockIdx.x;     // 0..NBLK-1
        g_p1[t*NBLK + blk] = S1;
        g_p2[t*NBLK + blk] = S2;
    }
}

// ---------------- 6: reduce partials -> folded BN coeffs (plain fp64) ----------------
__global__ void k_statsR(const float* __restrict__ bnw, const float* __restrict__ bnb){
    int h = blockIdx.x, t = threadIdx.x;   // 256 threads
    double s1=0.0, s2=0.0;
    for(int i=t; i<NBLK; i+=256){ s1 += g_p1[h*NBLK+i]; s2 += g_p2[h*NBLK+i]; }
    s1 = warpSumD(s1); s2 = warpSumD(s2);
    __shared__ double a1[8], a2[8];
    if((t&31)==0){ a1[t>>5]=s1; a2[t>>5]=s2; }
    __syncthreads();
    if(t==0){
        double S1=0.0, S2=0.0;
        #pragma unroll
        for(int u=0;u<8;u++){ S1+=a1[u]; S2+=a2[u]; }
        const double invc = 1.0/(double)(BB*NN*KK);
        double m = S1*invc;
        double var = S2*invc - m*m;
        double istd = 1.0/sqrt(var + 1e-5);
        float A = (float)(istd * (double)bnw[h]);
        g_bnA[h] = A;
        g_bnB[h] = (float)((double)bnb[h] - m*(double)A);
    }
}

// ---------------- 7: pass B — coalesced h-gathers; BN + dir-LeakyReLU + mean over k ----------------
// grid (NN/4, BB), block 256: t = nloc*64 + h
__global__ void k_passB(int c0){
    int b = blockIdx.y, t = threadIdx.x;
    int h = t & 63;
    int n = blockIdx.x*4 + (t >> 6);
    size_t base = (size_t)b*NN*HH;
    float4 q  = g_qf[base + (size_t)n*HH + h];
    float4 qd = g_qd[base + (size_t)n*HH + h];
    const int* ix = g_idx + (b*NN + n)*KK;
    float A = g_bnA[h], Bc = g_bnB[h];
    float ox=0.f, oy=0.f, oz=0.f;
    #pragma unroll 5
    for(int k=0;k<KK;k++){
        int m = ix[k];
        float4 y  = g_yf[base + (size_t)m*HH + h];
        float4 yD = g_yd[base + (size_t)m*HH + h];
        float px = y.x+q.x, py = y.y+q.y, pz = y.z+q.z;
        float dx = yD.x+qd.x, dy = yD.y+qd.y, dz = yD.z+qd.z;
        float ss = px*px + py*py + pz*pz;
        float nm = sqrtf(ss) + 1e-6f;
        float inv = __fdividef(1.f, nm);
        float sc = A + Bc*inv;
        px *= sc; py *= sc; pz *= sc;
        float dot = px*dx + py*dy + pz*dz;
        if(dot < 0.f){
            float cc = 0.8f*dot*__fdividef(1.f, dx*dx + dy*dy + dz*dz + 1e-6f);
            px -= cc*dx; py -= cc*dy; pz -= cc*dz;
        }
        ox += px; oy += py; oz += pz;
    }
    const float s = 1.f/(float)KK;
    int obase = b*CATSTR + (c0+h)*3*NN + n;
    g_cat[obase]        = ox*s;
    g_cat[obase+NN]     = oy*s;
    g_cat[obase+2*NN]   = oz*s;
}

// ---------------- 8: final p = wcf @ cat (f32x2) ----------------
__global__ void k_pgemm(const float* __restrict__ wcf){
    int b = blockIdx.z, h0 = blockIdx.y*64, col0 = blockIdx.x*64;
    __shared__ __align__(16) float sW[16][68];
    __shared__ __align__(16) float sX[16][64];
    int t = threadIdx.x;
    int r0 = (t>>4)<<2, c0 = (t&15)<<2;
    u64 acc2[4][2];
    #pragma unroll
    for(int ii=0;ii<4;ii++){ acc2[ii][0]=0ull; acc2[ii][1]=0ull; }
    const float* catb = g_cat + b*CATSTR;
    for(int cb=0; cb<CATC; cb+=16){
        for(int l=t; l<1024; l+=256){
            int i = l>>4, cc = l&15;
            sW[cc][i] = wcf[(h0+i)*CATC + cb + cc];
        }
        for(int l=t; l<1024; l+=256){
            int cc = l>>6, j = l&63;
            sX[cc][j] = catb[(cb+cc)*3072 + col0 + j];
        }
        __syncthreads();
        #pragma unroll
        for(int cc=0; cc<16; cc++){
            float4 av = *(const float4*)&sW[cc][r0];
            ulonglong2 bv = *(const ulonglong2*)&sX[cc][c0];
            u64 a0 = pack2(av.x), a1 = pack2(av.y), a2 = pack2(av.z), a3 = pack2(av.w);
            acc2[0][0] = ffma2(a0, bv.x, acc2[0][0]);
            acc2[0][1] = ffma2(a0, bv.y, acc2[0][1]);
            acc2[1][0] = ffma2(a1, bv.x, acc2[1][0]);
            acc2[1][1] = ffma2(a1, bv.y, acc2[1][1]);
            acc2[2][0] = ffma2(a2, bv.x, acc2[2][0]);
            acc2[2][1] = ffma2(a2, bv.y, acc2[2][1]);
            acc2[3][0] = ffma2(a3, bv.x, acc2[3][0]);
            acc2[3][1] = ffma2(a3, bv.y, acc2[3][1]);
        }
        __syncthreads();
    }
    float* pf = (float*)g_pf;
    #pragma unroll
    for(int ii=0;ii<4;ii++){
        int h = h0 + r0 + ii;
        float a0,a1,a2,a3;
        unpack2(acc2[ii][0], a0, a1);
        unpack2(acc2[ii][1], a2, a3);
        float vals[4] = {a0,a1,a2,a3};
        #pragma unroll
        for(int jj=0;jj<4;jj++){
            int col = col0 + c0 + jj;
            int n = col & 1023, comp = col >> 10;
            pf[(((b*CD)+h)*NN + n)*4 + comp] = vals[jj];
        }
    }
}

// ---------------- 9: final d = wcd @ cat ----------------
__global__ void k_dvec(const float* __restrict__ wcd){
    int i = blockIdx.x*256 + threadIdx.x;   // B*3072
    int b = i/3072, col = i - b*3072;
    const float* catb = g_cat + b*CATSTR;
    float s = 0.f;
    for(int c=0;c<CATC;c++) s = fmaf(wcd[c], catb[c*3072 + col], s);
    int n = col & 1023, comp = col >> 10;
    ((float*)g_df)[(b*NN+n)*4 + comp] = s;
}

// ---------------- 10: final BN stats (nm-form, double per element) ----------------
__global__ void k_fstats(const float* __restrict__ bw, const float* __restrict__ bb){
    int h = blockIdx.x, t = threadIdx.x;    // 256 threads
    double s1=0.0, s2=0.0;
    for(int i=t; i<BB*NN; i+=256){
        int b = i>>10, n = i&1023;
        float4 p = g_pf[((b*CD)+h)*NN + n];
        float ss = p.x*p.x + p.y*p.y + p.z*p.z;
        float nm = sqrtf(ss) + 1e-6f;
        double nd = (double)nm;
        s1 += nd; s2 += nd*nd;
    }
    __shared__ double sh1[8], sh2[8];
    s1 = warpSumD(s1); s2 = warpSumD(s2);
    if((t&31)==0){ sh1[t>>5]=s1; sh2[t>>5]=s2; }
    __syncthreads();
    if(t==0){
        double S1=0.0, S2=0.0;
        #pragma unroll
        for(int u=0;u<8;u++){ S1+=sh1[u]; S2+=sh2[u]; }
        const double invc = 1.0/(double)(BB*NN);
        double m = S1*invc;
        double var = S2*invc - m*m;
        double istd = 1.0/sqrt(var + 1e-5);
        float A = (float)(istd*(double)bw[h]);
        g_bnA[h] = A;
        g_bnB[h] = (float)((double)bb[h] - m*(double)A);
    }
}

// ---------------- 11: finalize — BN + leaky + mean over N ----------------
__global__ void k_final(float* __restrict__ out){
    int h = blockIdx.x, b = blockIdx.y;
    float A = g_bnA[h], Bc = g_bnB[h];
    float ox=0.f, oy=0.f, oz=0.f;
    for(int n=threadIdx.x; n<NN; n+=256){
        float4 p = g_pf[((b*CD)+h)*NN + n];
        float4 d = g_df[b*NN + n];
        float ss = p.x*p.x + p.y*p.y + p.z*p.z;
        float nm = sqrtf(ss) + 1e-6f;
        float r = __fdividef(1.f, nm);
        float sc = A + Bc*r;
        float px = p.x*sc, py = p.y*sc, pz = p.z*sc;
        float dot = px*d.x + py*d.y + pz*d.z;
        if(dot < 0.f){
            float cc = 0.8f*dot*__fdividef(1.f, d.x*d.x + d.y*d.y + d.z*d.z + 1e-6f);
            px -= cc*d.x; py -= cc*d.y; pz -= cc*d.z;
        }
        ox += px; oy += py; oz += pz;
    }
    __shared__ float sx[8], sy[8], sz[8];
    ox = warpSum(ox); oy = warpSum(oy); oz = warpSum(oz);
    int t = threadIdx.x;
    if((t&31)==0){ sx[t>>5]=ox; sy[t>>5]=oy; sz[t>>5]=oz; }
    __syncthreads();
    if(t==0){
        float X=0.f, Y=0.f, Z=0.f;
        #pragma unroll
        for(int u=0;u<8;u++){ X+=sx[u]; Y+=sy[u]; Z+=sz[u]; }
        const float s = 1.f/(float)NN;
        float* o = out + (b*CD + h)*3;
        o[0] = X*s; o[1] = Y*s; o[2] = Z*s;
    }
}

// ---------------- host orchestration ----------------
static void conv_layer(const float* in, int C, int bstr,
                       const float* wf, const float* wd,
                       const float* bnw, const float* bnb, int c0_out){
    int D = C*3;
    k_xx  <<<32, 256>>>(in, D, bstr);
    k_dist<<<dim3(16,16,BB), 256>>>(in, D, bstr);
    k_topk<<<BB*NN/8, 256>>>();
    k_yq  <<<dim3(NN/32, 2, BB), 192>>>(in, C, bstr, wf, wd);
    k_statsA<<<dim3(NN/4, BB), 256>>>();
    k_statsR<<<HH, 256>>>(bnw, bnb);
    k_passB<<<dim3(NN/4, BB), 256>>>(c0_out);
}

extern "C" void kernel_launch(void* const* d_in, const int* in_sizes, int n_in,
                              void* d_out, int out_size){
    const float* x    = (const float*)d_in[0];
    const float* w1f  = (const float*)d_in[1];
    const float* w1d  = (const float*)d_in[2];
    const float* bn1w = (const float*)d_in[3];
    const float* bn1b = (const float*)d_in[4];
    const float* w2f  = (const float*)d_in[5];
    const float* w2d  = (const float*)d_in[6];
    const float* bn2w = (const float*)d_in[7];
    const float* bn2b = (const float*)d_in[8];
    const float* w3f  = (const float*)d_in[9];
    const float* w3d  = (const float*)d_in[10];
    const float* bn3w = (const float*)d_in[11];
    const float* bn3b = (const float*)d_in[12];
    const float* w4f  = (const float*)d_in[13];
    const float* w4d  = (const float*)d_in[14];
    const float* bn4w = (const float*)d_in[15];
    const float* bn4b = (const float*)d_in[16];
    const float* wcf  = (const float*)d_in[17];
    const float* wcd  = (const float*)d_in[18];
    const float* bncw = (const float*)d_in[19];
    const float* bncb = (const float*)d_in[20];
    float* out = (float*)d_out;

    float *pts = nullptr, *cat = nullptr;
    cudaGetSymbolAddress((void**)&pts, g_pts);
    cudaGetSymbolAddress((void**)&cat, g_cat);

    k_transpose<<<32, 256>>>(x);

    conv_layer(pts, 1, 3*NN, w1f, w1d, bn1w, bn1b, 0);
    conv_layer(cat,            HH, CATSTR, w2f, w2d, bn2w, bn2b, HH);
    conv_layer(cat + HH*3*NN,  HH, CATSTR, w3f, w3d, bn3w, bn3b, 2*HH);
    conv_layer(cat + 2*HH*3*NN,HH, CATSTR, w4f, w4d, bn4w, bn4b, 3*HH);

    k_pgemm <<<dim3(3072/64, CD/64, BB), 256>>>(wcf);
    k_dvec  <<<BB*3072/256, 256>>>(wcd);
    k_fstats<<<CD, 256>>>(bncw, bncb);
    k_final <<<dim3(CD, BB), 256>>>(out);
}

// round 15
// speedup vs baseline: 1.0541x; 1.0341x over previous
#include <cuda_runtime.h>
#include <math.h>

#define BB 8
#define NN 1024
#define KK 20
#define HH 64
#define CD 128
#define CATC 256
#define CATSTR (CATC*3*NN)
#define NBLK 2048   // statsA partial blocks = (NN/4)*BB

typedef unsigned long long u64;

// ---------------- scratch ----------------
__device__ float  g_pts[BB*3*NN];
__device__ float  g_cat[BB*CATC*3*NN];
__device__ float  g_xx[BB*NN];
__device__ float  g_dist[BB*NN*NN];
__device__ int    g_idx[BB*NN*KK];
// h-contiguous layout: [b][n][h] float4
__device__ float4 g_yf[BB*NN*HH];
__device__ float4 g_qf[BB*NN*HH];
__device__ float4 g_yd[BB*NN*HH];
__device__ float4 g_qd[BB*NN*HH];
__device__ double g_p1[HH*NBLK], g_p2[HH*NBLK];   // partial Σnm, Σnm²
__device__ float  g_bnA[CD], g_bnB[CD];
__device__ float4 g_pf[BB*CD*NN];
__device__ float4 g_df[BB*NN];

__device__ __forceinline__ float warpSum(float v){
    #pragma unroll
    for(int o=16;o;o>>=1) v += __shfl_down_sync(0xffffffffu, v, o);
    return v;
}
__device__ __forceinline__ double warpSumD(double v){
    #pragma unroll
    for(int o=16;o;o>>=1) v += __shfl_down_sync(0xffffffffu, v, o);
    return v;
}

// packed f32x2 helpers (sm_103a)
__device__ __forceinline__ u64 ffma2(u64 a, u64 b, u64 c){
    u64 d;
    asm("fma.rn.f32x2 %0, %1, %2, %3;" : "=l"(d) : "l"(a), "l"(b), "l"(c));
    return d;
}
__device__ __forceinline__ u64 pack2(float x){
    u64 d;
    asm("mov.b64 %0, {%1, %1};" : "=l"(d) : "f"(x));
    return d;
}
__device__ __forceinline__ void unpack2(u64 d, float& lo, float& hi){
    asm("mov.b64 {%0, %1}, %2;" : "=f"(lo), "=f"(hi) : "l"(d));
}

// monotonic uint key for float ordering; -0.0 normalized so key order
// matches float compare exactly on finite floats
__device__ __forceinline__ unsigned fkey(float f){
    unsigned u = __float_as_uint(f);
    if(u == 0x80000000u) u = 0u;          // -0.0 -> +0.0
    return (u & 0x80000000u) ? ~u : (u | 0x80000000u);
}

// ---------------- 0: transpose x[B,N,3] -> pts[B,3,N] ----------------
__global__ void k_transpose(const float* __restrict__ x){
    int i = blockIdx.x*256 + threadIdx.x;
    if(i < BB*NN){
        int b = i>>10, n = i&1023;
        const float* src = x + (size_t)(b*NN+n)*3;
        g_pts[(b*3+0)*NN+n] = src[0];
        g_pts[(b*3+1)*NN+n] = src[1];
        g_pts[(b*3+2)*NN+n] = src[2];
    }
}

// ---------------- 1: squared norms per point ----------------
__global__ void k_xx(const float* __restrict__ in, int D, int bstr){
    int i = blockIdx.x*256 + threadIdx.x;
    int b = i>>10, n = i&1023;
    const float* fb = in + b*bstr;
    float s = 0.f;
    for(int d=0; d<D; d++){ float v = fb[d*NN+n]; s = fmaf(v,v,s); }
    g_xx[i] = s;
}

// ---------------- 2: neg pairwise distance (Gram), f32x2, FULL grid ----------------
__global__ void k_dist(const float* __restrict__ in, int D, int bstr){
    int b = blockIdx.z, n0 = blockIdx.y*64, m0 = blockIdx.x*64;
    __shared__ __align__(16) float sA[16][64];
    __shared__ __align__(16) float sB[16][64];
    int t = threadIdx.x;
    int r0 = (t>>4)<<2, c0 = (t&15)<<2;
    u64 acc2[4][2];
    #pragma unroll
    for(int ii=0;ii<4;ii++){ acc2[ii][0]=0ull; acc2[ii][1]=0ull; }
    const float* fb = in + b*bstr;
    for(int d0=0; d0<D; d0+=16){
        for(int l=t; l<1024; l+=256){
            int dd = l>>6, i = l&63, d = d0+dd;
            float va = (d<D) ? fb[d*NN + n0 + i] : 0.f;
            float vb = (d<D) ? fb[d*NN + m0 + i] : 0.f;
            sA[dd][i] = va; sB[dd][i] = vb;
        }
        __syncthreads();
        #pragma unroll
        for(int dd=0; dd<16; dd++){
            float4 av = *(const float4*)&sA[dd][r0];
            ulonglong2 bv = *(const ulonglong2*)&sB[dd][c0];
            u64 a0 = pack2(av.x), a1 = pack2(av.y), a2 = pack2(av.z), a3 = pack2(av.w);
            acc2[0][0] = ffma2(a0, bv.x, acc2[0][0]);
            acc2[0][1] = ffma2(a0, bv.y, acc2[0][1]);
            acc2[1][0] = ffma2(a1, bv.x, acc2[1][0]);
            acc2[1][1] = ffma2(a1, bv.y, acc2[1][1]);
            acc2[2][0] = ffma2(a2, bv.x, acc2[2][0]);
            acc2[2][1] = ffma2(a2, bv.y, acc2[2][1]);
            acc2[3][0] = ffma2(a3, bv.x, acc2[3][0]);
            acc2[3][1] = ffma2(a3, bv.y, acc2[3][1]);
        }
        __syncthreads();
    }
    float xn[4], xm[4];
    #pragma unroll
    for(int ii=0;ii<4;ii++) xn[ii] = g_xx[b*NN + n0 + r0 + ii];
    #pragma unroll
    for(int jj=0;jj<4;jj++) xm[jj] = g_xx[b*NN + m0 + c0 + jj];
    #pragma unroll
    for(int ii=0;ii<4;ii++){
        int n = n0 + r0 + ii;
        float a0,a1,a2,a3;
        unpack2(acc2[ii][0], a0, a1);
        unpack2(acc2[ii][1], a2, a3);
        float4 o;
        o.x = 2.f*a0 - xn[ii] - xm[0];
        o.y = 2.f*a1 - xn[ii] - xm[1];
        o.z = 2.f*a2 - xn[ii] - xm[2];
        o.w = 2.f*a3 - xn[ii] - xm[3];
        *(float4*)&g_dist[(size_t)(b*NN+n)*NN + m0 + c0] = o;
    }
}

// 4-chain ILP local argmax over 32 register keys (ties -> smallest index)
__device__ __forceinline__ void scan32(const unsigned* kv, unsigned& lk, int& li){
    unsigned k0=kv[0];  int i0=0;
    unsigned k1=kv[8];  int i1=8;
    unsigned k2=kv[16]; int i2=16;
    unsigned k3=kv[24]; int i3=24;
    #pragma unroll
    for(int j=1;j<8;j++){
        if(kv[j]    > k0){ k0=kv[j];    i0=j;    }
        if(kv[8+j]  > k1){ k1=kv[8+j];  i1=8+j;  }
        if(kv[16+j] > k2){ k2=kv[16+j]; i2=16+j; }
        if(kv[24+j] > k3){ k3=kv[24+j]; i3=24+j; }
    }
    if(k1 > k0){ k0=k1; i0=i1; }
    if(k3 > k2){ k2=k3; i2=i3; }
    if(k2 > k0){ k0=k2; i0=i2; }
    lk=k0; li=i0;
}

// ---------------- 3: top-20 per row — warp per row, REDUX argmax (-0.0 fixed) ----------------
__global__ void k_topk(){
    int row = blockIdx.x*8 + (threadIdx.x>>5);
    int lane = threadIdx.x & 31;
    const float* dr = g_dist + (size_t)row*NN;
    unsigned kv[32];
    #pragma unroll
    for(int j=0;j<32;j++) kv[j] = fkey(dr[lane + (j<<5)]);   // coalesced
    unsigned lk; int li;
    scan32(kv, lk, li);
    int* outp = g_idx + row*KK;
    #pragma unroll 1
    for(int kk=0; kk<KK; kk++){
        unsigned m = __reduce_max_sync(0xffffffffu, lk);
        unsigned cand = (lk == m) ? (unsigned)(lane + (li<<5)) : 0xffffffffu;
        unsigned bidx = __reduce_min_sync(0xffffffffu, cand);
        if(lane == 0) outp[kk] = (int)bidx;
        if((bidx & 31u) == (unsigned)lane){
            #pragma unroll
            for(int j=0;j<32;j++) if(j==li) kv[j] = 0u;
            scan32(kv, lk, li);
        }
    }
}

// ---------------- 4: tiny GEMMs y/q = W @ x (f32x2), PAIR-MERGED ----------------
// grid (N/32, pair 0..1, B); block 192 = 64h x 3comp
__global__ void k_yq(const float* __restrict__ in, int C, int bstr,
                     const float* __restrict__ wf, const float* __restrict__ wd){
    int b = blockIdx.z, pair = blockIdx.y, n0 = blockIdx.x*32;
    __shared__ __align__(16) float xs[HH*3*32];
    __shared__ float os[3][HH][33];
    int t = threadIdx.x;                  // 192
    const float* xb = in + b*bstr;
    int R = C*3;
    for(int l=t; l<R*32; l+=192){
        int row = l>>5, col = l&31;
        xs[l] = xb[row*NN + n0 + col];
    }
    __syncthreads();
    int h = t/3, comp = t - h*3;
    const float* w = pair ? wd : wf;
    int twoC = 2*C;
    #pragma unroll 1
    for(int sub=0; sub<2; sub++){
        u64 acc[16];
        #pragma unroll
        for(int j=0;j<16;j++) acc[j]=0ull;
        for(int c=0;c<C;c++){
            float wv = w[h*twoC + c];
            if(sub) wv = w[h*twoC + C + c] - wv;
            u64 w2 = pack2(wv);
            const u64* xr = (const u64*)(xs + (c*3 + comp)*32);
            #pragma unroll
            for(int j=0;j<16;j++) acc[j] = ffma2(w2, xr[j], acc[j]);
        }
        #pragma unroll
        for(int j=0;j<16;j++){
            float f0,f1;
            unpack2(acc[j], f0, f1);
            os[comp][h][2*j]   = f0;
            os[comp][h][2*j+1] = f1;
        }
        __syncthreads();
        float4* outp = (pair==0 ? (sub==0 ? g_yf : g_qf)
                                : (sub==0 ? g_yd : g_qd))
                       + ((size_t)b*NN + n0)*HH;
        for(int idx=t; idx<HH*32; idx+=192){
            int n = idx>>6, h2 = idx&63;
            outp[(size_t)n*HH + h2] = make_float4(os[0][h2][n], os[1][h2][n], os[2][h2][n], 0.f);
        }
        __syncthreads();
    }
}

// ---------------- 5: pass A — BN stats; h-gathers; nm-form double; smem ix ----------------
// grid (NN/4, BB), block 256: t = nloc*64 + h
__global__ void k_statsA(){
    int b = blockIdx.y, t = threadIdx.x;
    int h = t & 63, nloc = t >> 6;
    int n = blockIdx.x*4 + nloc;
    __shared__ int six[4][KK];
    if(t < 4*KK){
        int nl = t/KK, k = t - nl*KK;
        six[nl][k] = g_idx[(b*NN + blockIdx.x*4 + nl)*KK + k];
    }
    const float4* yf = g_yf + (size_t)b*NN*HH;
    float4 q = g_qf[((size_t)b*NN + n)*HH + h];
    __syncthreads();
    double s1 = 0.0, s2 = 0.0;
    #pragma unroll
    for(int k=0;k<KK;k++){
        int m = six[nloc][k];
        float4 y = yf[(size_t)m*HH + h];
        float px = y.x+q.x, py = y.y+q.y, pz = y.z+q.z;
        float ss = px*px + py*py + pz*pz;
        float nm = sqrtf(ss) + 1e-6f;        // exact reference norm
        double nd = (double)nm;
        s1 += nd; s2 += nd*nd;               // nm-form (frozen; eps-algebra banned)
    }
    __shared__ double sr[256], ssd[256];
    sr[t] = s1; ssd[t] = s2;
    __syncthreads();
    if(t < 64){
        double S1 = sr[t] + sr[t+64] + sr[t+128] + sr[t+192];
        double S2 = ssd[t] + ssd[t+64] + ssd[t+128] + ssd[t+192];
        int blk = b*(NN/4) + blockIdx.x;     // 0..NBLK-1
        g_p1[t*NBLK + blk] = S1;
        g_p2[t*NBLK + blk] = S2;
    }
}

// ---------------- 6: reduce partials -> folded BN coeffs (plain fp64) ----------------
__global__ void k_statsR(const float* __restrict__ bnw, const float* __restrict__ bnb){
    int h = blockIdx.x, t = threadIdx.x;   // 256 threads
    double s1=0.0, s2=0.0;
    for(int i=t; i<NBLK; i+=256){ s1 += g_p1[h*NBLK+i]; s2 += g_p2[h*NBLK+i]; }
    s1 = warpSumD(s1); s2 = warpSumD(s2);
    __shared__ double a1[8], a2[8];
    if((t&31)==0){ a1[t>>5]=s1; a2[t>>5]=s2; }
    __syncthreads();
    if(t==0){
        double S1=0.0, S2=0.0;
        #pragma unroll
        for(int u=0;u<8;u++){ S1+=a1[u]; S2+=a2[u]; }
        const double invc = 1.0/(double)(BB*NN*KK);
        double m = S1*invc;
        double var = S2*invc - m*m;
        double istd = 1.0/sqrt(var + 1e-5);
        float A = (float)(istd * (double)bnw[h]);
        g_bnA[h] = A;
        g_bnB[h] = (float)((double)bnb[h] - m*(double)A);
    }
}

// ---------------- 7: pass B — h-gathers; BN + dir-LeakyReLU + mean over k; smem ix ----------------
// grid (NN/4, BB), block 256: t = nloc*64 + h
__global__ void k_passB(int c0){
    int b = blockIdx.y, t = threadIdx.x;
    int h = t & 63;
    int nloc = t >> 6;
    int n = blockIdx.x*4 + nloc;
    __shared__ int six[4][KK];
    if(t < 4*KK){
        int nl = t/KK, k = t - nl*KK;
        six[nl][k] = g_idx[(b*NN + blockIdx.x*4 + nl)*KK + k];
    }
    size_t base = (size_t)b*NN*HH;
    float4 q  = g_qf[base + (size_t)n*HH + h];
    float4 qd = g_qd[base + (size_t)n*HH + h];
    float A = g_bnA[h], Bc = g_bnB[h];
    __syncthreads();
    float ox=0.f, oy=0.f, oz=0.f;
    #pragma unroll 5
    for(int k=0;k<KK;k++){
        int m = six[nloc][k];
        float4 y  = g_yf[base + (size_t)m*HH + h];
        float4 yD = g_yd[base + (size_t)m*HH + h];
        float px = y.x+q.x, py = y.y+q.y, pz = y.z+q.z;
        float dx = yD.x+qd.x, dy = yD.y+qd.y, dz = yD.z+qd.z;
        float ss = px*px + py*py + pz*pz;
        float nm = sqrtf(ss) + 1e-6f;
        float inv = __fdividef(1.f, nm);
        float sc = A + Bc*inv;
        px *= sc; py *= sc; pz *= sc;
        float dot = px*dx + py*dy + pz*dz;
        if(dot < 0.f){
            float cc = 0.8f*dot*__fdividef(1.f, dx*dx + dy*dy + dz*dz + 1e-6f);
            px -= cc*dx; py -= cc*dy; pz -= cc*dz;
        }
        ox += px; oy += py; oz += pz;
    }
    const float s = 1.f/(float)KK;
    int obase = b*CATSTR + (c0+h)*3*NN + n;
    g_cat[obase]        = ox*s;
    g_cat[obase+NN]     = oy*s;
    g_cat[obase+2*NN]   = oz*s;
}

// ---------------- 8: final p = wcf @ cat (f32x2) ----------------
__global__ void k_pgemm(const float* __restrict__ wcf){
    int b = blockIdx.z, h0 = blockIdx.y*64, col0 = blockIdx.x*64;
    __shared__ __align__(16) float sW[16][68];
    __shared__ __align__(16) float sX[16][64];
    int t = threadIdx.x;
    int r0 = (t>>4)<<2, c0 = (t&15)<<2;
    u64 acc2[4][2];
    #pragma unroll
    for(int ii=0;ii<4;ii++){ acc2[ii][0]=0ull; acc2[ii][1]=0ull; }
    const float* catb = g_cat + b*CATSTR;
    for(int cb=0; cb<CATC; cb+=16){
        for(int l=t; l<1024; l+=256){
            int i = l>>4, cc = l&15;
            sW[cc][i] = wcf[(h0+i)*CATC + cb + cc];
        }
        for(int l=t; l<1024; l+=256){
            int cc = l>>6, j = l&63;
            sX[cc][j] = catb[(cb+cc)*3072 + col0 + j];
        }
        __syncthreads();
        #pragma unroll
        for(int cc=0; cc<16; cc++){
            float4 av = *(const float4*)&sW[cc][r0];
            ulonglong2 bv = *(const ulonglong2*)&sX[cc][c0];
            u64 a0 = pack2(av.x), a1 = pack2(av.y), a2 = pack2(av.z), a3 = pack2(av.w);
            acc2[0][0] = ffma2(a0, bv.x, acc2[0][0]);
            acc2[0][1] = ffma2(a0, bv.y, acc2[0][1]);
            acc2[1][0] = ffma2(a1, bv.x, acc2[1][0]);
            acc2[1][1] = ffma2(a1, bv.y, acc2[1][1]);
            acc2[2][0] = ffma2(a2, bv.x, acc2[2][0]);
            acc2[2][1] = ffma2(a2, bv.y, acc2[2][1]);
            acc2[3][0] = ffma2(a3, bv.x, acc2[3][0]);
            acc2[3][1] = ffma2(a3, bv.y, acc2[3][1]);
        }
        __syncthreads();
    }
    float* pf = (float*)g_pf;
    #pragma unroll
    for(int ii=0;ii<4;ii++){
        int h = h0 + r0 + ii;
        float a0,a1,a2,a3;
        unpack2(acc2[ii][0], a0, a1);
        unpack2(acc2[ii][1], a2, a3);
        float vals[4] = {a0,a1,a2,a3};
        #pragma unroll
        for(int jj=0;jj<4;jj++){
            int col = col0 + c0 + jj;
            int n = col & 1023, comp = col >> 10;
            pf[(((b*CD)+h)*NN + n)*4 + comp] = vals[jj];
        }
    }
}

// ---------------- 9: final d = wcd @ cat ----------------
__global__ void k_dvec(const float* __restrict__ wcd){
    int i = blockIdx.x*256 + threadIdx.x;   // B*3072
    int b = i/3072, col = i - b*3072;
    const float* catb = g_cat + b*CATSTR;
    float s = 0.f;
    for(int c=0;c<CATC;c++) s = fmaf(wcd[c], catb[c*3072 + col], s);
    int n = col & 1023, comp = col >> 10;
    ((float*)g_df)[(b*NN+n)*4 + comp] = s;
}

// ---------------- 10: final BN stats (nm-form, double per element) ----------------
__global__ void k_fstats(const float* __restrict__ bw, const float* __restrict__ bb){
    int h = blockIdx.x, t = threadIdx.x;    // 256 threads
    double s1=0.0, s2=0.0;
    for(int i=t; i<BB*NN; i+=256){
        int b = i>>10, n = i&1023;
        float4 p = g_pf[((b*CD)+h)*NN + n];
        float ss = p.x*p.x + p.y*p.y + p.z*p.z;
        float nm = sqrtf(ss) + 1e-6f;
        double nd = (double)nm;
        s1 += nd; s2 += nd*nd;
    }
    __shared__ double sh1[8], sh2[8];
    s1 = warpSumD(s1); s2 = warpSumD(s2);
    if((t&31)==0){ sh1[t>>5]=s1; sh2[t>>5]=s2; }
    __syncthreads();
    if(t==0){
        double S1=0.0, S2=0.0;
        #pragma unroll
        for(int u=0;u<8;u++){ S1+=sh1[u]; S2+=sh2[u]; }
        const double invc = 1.0/(double)(BB*NN);
        double m = S1*invc;
        double var = S2*invc - m*m;
        double istd = 1.0/sqrt(var + 1e-5);
        float A = (float)(istd*(double)bw[h]);
        g_bnA[h] = A;
        g_bnB[h] = (float)((double)bb[h] - m*(double)A);
    }
}

// ---------------- 11: finalize — BN + leaky + mean over N ----------------
__global__ void k_final(float* __restrict__ out){
    int h = blockIdx.x, b = blockIdx.y;
    float A = g_bnA[h], Bc = g_bnB[h];
    float ox=0.f, oy=0.f, oz=0.f;
    for(int n=threadIdx.x; n<NN; n+=256){
        float4 p = g_pf[((b*CD)+h)*NN + n];
        float4 d = g_df[b*NN + n];
        float ss = p.x*p.x + p.y*p.y + p.z*p.z;
        float nm = sqrtf(ss) + 1e-6f;
        float r = __fdividef(1.f, nm);
        float sc = A + Bc*r;
        float px = p.x*sc, py = p.y*sc, pz = p.z*sc;
        float dot = px*d.x + py*d.y + pz*d.z;
        if(dot < 0.f){
            float cc = 0.8f*dot*__fdividef(1.f, d.x*d.x + d.y*d.y + d.z*d.z + 1e-6f);
            px -= cc*d.x; py -= cc*d.y; pz -= cc*d.z;
        }
        ox += px; oy += py; oz += pz;
    }
    __shared__ float sx[8], sy[8], sz[8];
    ox = warpSum(ox); oy = warpSum(oy); oz = warpSum(oz);
    int t = threadIdx.x;
    if((t&31)==0){ sx[t>>5]=ox; sy[t>>5]=oy; sz[t>>5]=oz; }
    __syncthreads();
    if(t==0){
        float X=0.f, Y=0.f, Z=0.f;
        #pragma unroll
        for(int u=0;u<8;u++){ X+=sx[u]; Y+=sy[u]; Z+=sz[u]; }
        const float s = 1.f/(float)NN;
        float* o = out + (b*CD + h)*3;
        o[0] = X*s; o[1] = Y*s; o[2] = Z*s;
    }
}

// ---------------- host orchestration ----------------
static void conv_layer(const float* in, int C, int bstr,
                       const float* wf, const float* wd,
                       const float* bnw, const float* bnb, int c0_out){
    int D = C*3;
    k_xx  <<<32, 256>>>(in, D, bstr);
    k_dist<<<dim3(16,16,BB), 256>>>(in, D, bstr);
    k_topk<<<BB*NN/8, 256>>>();
    k_yq  <<<dim3(NN/32, 2, BB), 192>>>(in, C, bstr, wf, wd);
    k_statsA<<<dim3(NN/4, BB), 256>>>();
    k_statsR<<<HH, 256>>>(bnw, bnb);
    k_passB<<<dim3(NN/4, BB), 256>>>(c0_out);
}

extern "C" void kernel_launch(void* const* d_in, const int* in_sizes, int n_in,
                              void* d_out, int out_size){
    const float* x    = (const float*)d_in[0];
    const float* w1f  = (const float*)d_in[1];
    const float* w1d  = (const float*)d_in[2];
    const float* bn1w = (const float*)d_in[3];
    const float* bn1b = (const float*)d_in[4];
    const float* w2f  = (const float*)d_in[5];
    const float* w2d  = (const float*)d_in[6];
    const float* bn2w = (const float*)d_in[7];
    const float* bn2b = (const float*)d_in[8];
    const float* w3f  = (const float*)d_in[9];
    const float* w3d  = (const float*)d_in[10];
    const float* bn3w = (const float*)d_in[11];
    const float* bn3b = (const float*)d_in[12];
    const float* w4f  = (const float*)d_in[13];
    const float* w4d  = (const float*)d_in[14];
    const float* bn4w = (const float*)d_in[15];
    const float* bn4b = (const float*)d_in[16];
    const float* wcf  = (const float*)d_in[17];
    const float* wcd  = (const float*)d_in[18];
    const float* bncw = (const float*)d_in[19];
    const float* bncb = (const float*)d_in[20];
    float* out = (float*)d_out;

    float *pts = nullptr, *cat = nullptr;
    cudaGetSymbolAddress((void**)&pts, g_pts);
    cudaGetSymbolAddress((void**)&cat, g_cat);

    k_transpose<<<32, 256>>>(x);

    conv_layer(pts, 1, 3*NN, w1f, w1d, bn1w, bn1b, 0);
    conv_layer(cat,            HH, CATSTR, w2f, w2d, bn2w, bn2b, HH);
    conv_layer(cat + HH*3*NN,  HH, CATSTR, w3f, w3d, bn3w, bn3b, 2*HH);
    conv_layer(cat + 2*HH*3*NN,HH, CATSTR, w4f, w4d, bn4w, bn4b, 3*HH);

    k_pgemm <<<dim3(3072/64, CD/64, BB), 256>>>(wcf);
    k_dvec  <<<BB*3072/256, 256>>>(wcd);
    k_fstats<<<CD, 256>>>(bncw, bncb);
    k_final <<<dim3(CD, BB), 256>>>(out);
}

// round 16
// speedup vs baseline: 1.0716x; 1.0166x over previous
#include <cuda_runtime.h>
#include <math.h>

#define BB 8
#define NN 1024
#define KK 20
#define HH 64
#define CD 128
#define CATC 256
#define CATSTR (CATC*3*NN)
#define NBLK 2048   // statsA partial blocks = (NN/4)*BB

typedef unsigned long long u64;

// ---------------- scratch ----------------
__device__ float  g_pts[BB*3*NN];
__device__ float  g_cat[BB*CATC*3*NN];
__device__ float  g_dist[BB*NN*NN];
__device__ int    g_idx[BB*NN*KK];
// h-contiguous layout: [b][n][h] float4
__device__ float4 g_yf[BB*NN*HH];
__device__ float4 g_qf[BB*NN*HH];
__device__ float4 g_yd[BB*NN*HH];
__device__ float4 g_qd[BB*NN*HH];
__device__ double g_p1[NBLK*HH], g_p2[NBLK*HH];   // [blk][h] coalesced partials
__device__ float  g_bnA[CD], g_bnB[CD];
__device__ float4 g_pf[BB*CD*NN];
__device__ float4 g_df[BB*NN];

__device__ __forceinline__ float warpSum(float v){
    #pragma unroll
    for(int o=16;o;o>>=1) v += __shfl_down_sync(0xffffffffu, v, o);
    return v;
}
__device__ __forceinline__ double warpSumD(double v){
    #pragma unroll
    for(int o=16;o;o>>=1) v += __shfl_down_sync(0xffffffffu, v, o);
    return v;
}

// packed f32x2 helpers (sm_103a)
__device__ __forceinline__ u64 ffma2(u64 a, u64 b, u64 c){
    u64 d;
    asm("fma.rn.f32x2 %0, %1, %2, %3;" : "=l"(d) : "l"(a), "l"(b), "l"(c));
    return d;
}
__device__ __forceinline__ u64 pack2(float x){
    u64 d;
    asm("mov.b64 %0, {%1, %1};" : "=l"(d) : "f"(x));
    return d;
}
__device__ __forceinline__ void unpack2(u64 d, float& lo, float& hi){
    asm("mov.b64 {%0, %1}, %2;" : "=f"(lo), "=f"(hi) : "l"(d));
}

// monotonic uint key; -0.0 normalized so order matches float compare exactly
__device__ __forceinline__ unsigned fkey(float f){
    unsigned u = __float_as_uint(f);
    if(u == 0x80000000u) u = 0u;
    return (u & 0x80000000u) ? ~u : (u | 0x80000000u);
}

// ---------------- 0: transpose x[B,N,3] -> pts[B,3,N] ----------------
__global__ void k_transpose(const float* __restrict__ x){
    int i = blockIdx.x*256 + threadIdx.x;
    if(i < BB*NN){
        int b = i>>10, n = i&1023;
        const float* src = x + (size_t)(b*NN+n)*3;
        g_pts[(b*3+0)*NN+n] = src[0];
        g_pts[(b*3+1)*NN+n] = src[1];
        g_pts[(b*3+2)*NN+n] = src[2];
    }
}

// ---------------- 2: Gram + fused norms, f32x2, float4 staging ----------------
// norm accumulation order identical to the old k_xx (sequential d, zeros for d>=D are exact no-ops)
__global__ void k_dist(const float* __restrict__ in, int D, int bstr){
    int b = blockIdx.z, n0 = blockIdx.y*64, m0 = blockIdx.x*64;
    __shared__ __align__(16) float sA[16][64];
    __shared__ __align__(16) float sB[16][64];
    __shared__ float sxn[64], sxm[64];
    int t = threadIdx.x;
    int r0 = (t>>4)<<2, c0 = (t&15)<<2;
    u64 acc2[4][2];
    #pragma unroll
    for(int ii=0;ii<4;ii++){ acc2[ii][0]=0ull; acc2[ii][1]=0ull; }
    float rn = 0.f;
    const float* fb = in + b*bstr;
    int sdd = t>>4, si4 = (t&15)<<2;
    for(int d0=0; d0<D; d0+=16){
        int d = d0 + sdd;
        float4 va = make_float4(0.f,0.f,0.f,0.f), vb = va;
        if(d < D){
            va = *(const float4*)&fb[d*NN + n0 + si4];
            vb = *(const float4*)&fb[d*NN + m0 + si4];
        }
        *(float4*)&sA[sdd][si4] = va;
        *(float4*)&sB[sdd][si4] = vb;
        __syncthreads();
        if(t < 64){
            #pragma unroll
            for(int dd=0;dd<16;dd++){ float v = sA[dd][t]; rn = fmaf(v,v,rn); }
        } else if(t < 128){
            int c = t-64;
            #pragma unroll
            for(int dd=0;dd<16;dd++){ float v = sB[dd][c]; rn = fmaf(v,v,rn); }
        }
        #pragma unroll
        for(int dd=0; dd<16; dd++){
            float4 av = *(const float4*)&sA[dd][r0];
            ulonglong2 bv = *(const ulonglong2*)&sB[dd][c0];
            u64 a0 = pack2(av.x), a1 = pack2(av.y), a2 = pack2(av.z), a3 = pack2(av.w);
            acc2[0][0] = ffma2(a0, bv.x, acc2[0][0]);
            acc2[0][1] = ffma2(a0, bv.y, acc2[0][1]);
            acc2[1][0] = ffma2(a1, bv.x, acc2[1][0]);
            acc2[1][1] = ffma2(a1, bv.y, acc2[1][1]);
            acc2[2][0] = ffma2(a2, bv.x, acc2[2][0]);
            acc2[2][1] = ffma2(a2, bv.y, acc2[2][1]);
            acc2[3][0] = ffma2(a3, bv.x, acc2[3][0]);
            acc2[3][1] = ffma2(a3, bv.y, acc2[3][1]);
        }
        __syncthreads();
    }
    if(t < 64) sxn[t] = rn;
    else if(t < 128) sxm[t-64] = rn;
    __syncthreads();
    float xn[4], xm[4];
    #pragma unroll
    for(int ii=0;ii<4;ii++) xn[ii] = sxn[r0 + ii];
    #pragma unroll
    for(int jj=0;jj<4;jj++) xm[jj] = sxm[c0 + jj];
    #pragma unroll
    for(int ii=0;ii<4;ii++){
        int n = n0 + r0 + ii;
        float a0,a1,a2,a3;
        unpack2(acc2[ii][0], a0, a1);
        unpack2(acc2[ii][1], a2, a3);
        float4 o;
        o.x = 2.f*a0 - xn[ii] - xm[0];
        o.y = 2.f*a1 - xn[ii] - xm[1];
        o.z = 2.f*a2 - xn[ii] - xm[2];
        o.w = 2.f*a3 - xn[ii] - xm[3];
        *(float4*)&g_dist[(size_t)(b*NN+n)*NN + m0 + c0] = o;
    }
}

// 4-chain ILP local argmax over 32 register keys (ties -> smallest index)
__device__ __forceinline__ void scan32(const unsigned* kv, unsigned& lk, int& li){
    unsigned k0=kv[0];  int i0=0;
    unsigned k1=kv[8];  int i1=8;
    unsigned k2=kv[16]; int i2=16;
    unsigned k3=kv[24]; int i3=24;
    #pragma unroll
    for(int j=1;j<8;j++){
        if(kv[j]    > k0){ k0=kv[j];    i0=j;    }
        if(kv[8+j]  > k1){ k1=kv[8+j];  i1=8+j;  }
        if(kv[16+j] > k2){ k2=kv[16+j]; i2=16+j; }
        if(kv[24+j] > k3){ k3=kv[24+j]; i3=24+j; }
    }
    if(k1 > k0){ k0=k1; i0=i1; }
    if(k3 > k2){ k2=k3; i2=i3; }
    if(k2 > k0){ k0=k2; i0=i2; }
    lk=k0; li=i0;
}

// ---------------- 3: top-20 per row — warp per row, REDUX argmax ----------------
__global__ void k_topk(){
    int row = blockIdx.x*8 + (threadIdx.x>>5);
    int lane = threadIdx.x & 31;
    const float* dr = g_dist + (size_t)row*NN;
    unsigned kv[32];
    #pragma unroll
    for(int j=0;j<32;j++) kv[j] = fkey(dr[lane + (j<<5)]);   // coalesced
    unsigned lk; int li;
    scan32(kv, lk, li);
    int* outp = g_idx + row*KK;
    #pragma unroll 1
    for(int kk=0; kk<KK; kk++){
        unsigned m = __reduce_max_sync(0xffffffffu, lk);
        unsigned cand = (lk == m) ? (unsigned)(lane + (li<<5)) : 0xffffffffu;
        unsigned bidx = __reduce_min_sync(0xffffffffu, cand);
        if(lane == 0) outp[kk] = (int)bidx;
        if((bidx & 31u) == (unsigned)lane){
            #pragma unroll
            for(int j=0;j<32;j++) if(j==li) kv[j] = 0u;
            scan32(kv, lk, li);
        }
    }
}

// ---------------- 4: tiny GEMMs y/q = W @ x (f32x2), PAIR-MERGED ----------------
// grid (N/32, pair 0..1, B); block 192 = 64h x 3comp
__global__ void k_yq(const float* __restrict__ in, int C, int bstr,
                     const float* __restrict__ wf, const float* __restrict__ wd){
    int b = blockIdx.z, pair = blockIdx.y, n0 = blockIdx.x*32;
    __shared__ __align__(16) float xs[HH*3*32];
    __shared__ float os[3][HH][33];
    int t = threadIdx.x;                  // 192
    const float* xb = in + b*bstr;
    int R = C*3;
    for(int l=t; l<R*32; l+=192){
        int row = l>>5, col = l&31;
        xs[l] = xb[row*NN + n0 + col];
    }
    __syncthreads();
    int h = t/3, comp = t - h*3;
    const float* w = pair ? wd : wf;
    int twoC = 2*C;
    #pragma unroll 1
    for(int sub=0; sub<2; sub++){
        u64 acc[16];
        #pragma unroll
        for(int j=0;j<16;j++) acc[j]=0ull;
        for(int c=0;c<C;c++){
            float wv = w[h*twoC + c];
            if(sub) wv = w[h*twoC + C + c] - wv;
            u64 w2 = pack2(wv);
            const u64* xr = (const u64*)(xs + (c*3 + comp)*32);
            #pragma unroll
            for(int j=0;j<16;j++) acc[j] = ffma2(w2, xr[j], acc[j]);
        }
        #pragma unroll
        for(int j=0;j<16;j++){
            float f0,f1;
            unpack2(acc[j], f0, f1);
            os[comp][h][2*j]   = f0;
            os[comp][h][2*j+1] = f1;
        }
        __syncthreads();
        float4* outp = (pair==0 ? (sub==0 ? g_yf : g_qf)
                                : (sub==0 ? g_yd : g_qd))
                       + ((size_t)b*NN + n0)*HH;
        for(int idx=t; idx<HH*32; idx+=192){
            int n = idx>>6, h2 = idx&63;
            outp[(size_t)n*HH + h2] = make_float4(os[0][h2][n], os[1][h2][n], os[2][h2][n], 0.f);
        }
        __syncthreads();
    }
}

// ---------------- 5: pass A — BN stats; h-gathers; nm-form double; smem ix; coalesced partials ----------------
// grid (NN/4, BB), block 256: t = nloc*64 + h
__global__ void k_statsA(){
    int b = blockIdx.y, t = threadIdx.x;
    int h = t & 63, nloc = t >> 6;
    int n = blockIdx.x*4 + nloc;
    __shared__ int six[4][KK];
    if(t < 4*KK){
        int nl = t/KK, k = t - nl*KK;
        six[nl][k] = g_idx[(b*NN + blockIdx.x*4 + nl)*KK + k];
    }
    const float4* yf = g_yf + (size_t)b*NN*HH;
    float4 q = g_qf[((size_t)b*NN + n)*HH + h];
    __syncthreads();
    double s1 = 0.0, s2 = 0.0;
    #pragma unroll
    for(int k=0;k<KK;k++){
        int m = six[nloc][k];
        float4 y = yf[(size_t)m*HH + h];
        float px = y.x+q.x, py = y.y+q.y, pz = y.z+q.z;
        float ss = px*px + py*py + pz*pz;
        float nm = sqrtf(ss) + 1e-6f;        // exact reference norm
        double nd = (double)nm;
        s1 += nd; s2 += nd*nd;               // nm-form (frozen; eps-algebra banned)
    }
    __shared__ double sr[256], ssd[256];
    sr[t] = s1; ssd[t] = s2;
    __syncthreads();
    if(t < 64){
        double S1 = sr[t] + sr[t+64] + sr[t+128] + sr[t+192];
        double S2 = ssd[t] + ssd[t+64] + ssd[t+128] + ssd[t+192];
        int blk = b*(NN/4) + blockIdx.x;     // 0..NBLK-1
        g_p1[blk*64 + t] = S1;               // coalesced
        g_p2[blk*64 + t] = S2;
    }
}

// ---------------- 6: reduce partials -> folded BN coeffs (plain fp64) ----------------
__global__ void k_statsR(const float* __restrict__ bnw, const float* __restrict__ bnb){
    int h = blockIdx.x, t = threadIdx.x;   // 256 threads
    double s1=0.0, s2=0.0;
    for(int i=t; i<NBLK; i+=256){ s1 += g_p1[i*64+h]; s2 += g_p2[i*64+h]; }
    s1 = warpSumD(s1); s2 = warpSumD(s2);
    __shared__ double a1[8], a2[8];
    if((t&31)==0){ a1[t>>5]=s1; a2[t>>5]=s2; }
    __syncthreads();
    if(t==0){
        double S1=0.0, S2=0.0;
        #pragma unroll
        for(int u=0;u<8;u++){ S1+=a1[u]; S2+=a2[u]; }
        const double invc = 1.0/(double)(BB*NN*KK);
        double m = S1*invc;
        double var = S2*invc - m*m;
        double istd = 1.0/sqrt(var + 1e-5);
        float A = (float)(istd * (double)bnw[h]);
        g_bnA[h] = A;
        g_bnB[h] = (float)((double)bnb[h] - m*(double)A);
    }
}

// ---------------- 7: pass B — h-gathers; BN + dir-LeakyReLU + mean over k; smem ix ----------------
// grid (NN/4, BB), block 256: t = nloc*64 + h
__global__ void k_passB(int c0){
    int b = blockIdx.y, t = threadIdx.x;
    int h = t & 63;
    int nloc = t >> 6;
    int n = blockIdx.x*4 + nloc;
    __shared__ int six[4][KK];
    if(t < 4*KK){
        int nl = t/KK, k = t - nl*KK;
        six[nl][k] = g_idx[(b*NN + blockIdx.x*4 + nl)*KK + k];
    }
    size_t base = (size_t)b*NN*HH;
    float4 q  = g_qf[base + (size_t)n*HH + h];
    float4 qd = g_qd[base + (size_t)n*HH + h];
    float A = g_bnA[h], Bc = g_bnB[h];
    __syncthreads();
    float ox=0.f, oy=0.f, oz=0.f;
    #pragma unroll 5
    for(int k=0;k<KK;k++){
        int m = six[nloc][k];
        float4 y  = g_yf[base + (size_t)m*HH + h];
        float4 yD = g_yd[base + (size_t)m*HH + h];
        float px = y.x+q.x, py = y.y+q.y, pz = y.z+q.z;
        float dx = yD.x+qd.x, dy = yD.y+qd.y, dz = yD.z+qd.z;
        float ss = px*px + py*py + pz*pz;
        float nm = sqrtf(ss) + 1e-6f;
        float inv = __fdividef(1.f, nm);
        float sc = A + Bc*inv;
        px *= sc; py *= sc; pz *= sc;
        float dot = px*dx + py*dy + pz*dz;
        if(dot < 0.f){
            float cc = 0.8f*dot*__fdividef(1.f, dx*dx + dy*dy + dz*dz + 1e-6f);
            px -= cc*dx; py -= cc*dy; pz -= cc*dz;
        }
        ox += px; oy += py; oz += pz;
    }
    const float s = 1.f/(float)KK;
    int obase = b*CATSTR + (c0+h)*3*NN + n;
    g_cat[obase]        = ox*s;
    g_cat[obase+NN]     = oy*s;
    g_cat[obase+2*NN]   = oz*s;
}

// ---------------- 8: final p = wcf @ cat (f32x2) ----------------
__global__ void k_pgemm(const float* __restrict__ wcf){
    int b = blockIdx.z, h0 = blockIdx.y*64, col0 = blockIdx.x*64;
    __shared__ __align__(16) float sW[16][68];
    __shared__ __align__(16) float sX[16][64];
    int t = threadIdx.x;
    int r0 = (t>>4)<<2, c0 = (t&15)<<2;
    u64 acc2[4][2];
    #pragma unroll
    for(int ii=0;ii<4;ii++){ acc2[ii][0]=0ull; acc2[ii][1]=0ull; }
    const float* catb = g_cat + b*CATSTR;
    for(int cb=0; cb<CATC; cb+=16){
        for(int l=t; l<1024; l+=256){
            int i = l>>4, cc = l&15;
            sW[cc][i] = wcf[(h0+i)*CATC + cb + cc];
        }
        for(int l=t; l<1024; l+=256){
            int cc = l>>6, j = l&63;
            sX[cc][j] = catb[(cb+cc)*3072 + col0 + j];
        }
        __syncthreads();
        #pragma unroll
        for(int cc=0; cc<16; cc++){
            float4 av = *(const float4*)&sW[cc][r0];
            ulonglong2 bv = *(const ulonglong2*)&sX[cc][c0];
            u64 a0 = pack2(av.x), a1 = pack2(av.y), a2 = pack2(av.z), a3 = pack2(av.w);
            acc2[0][0] = ffma2(a0, bv.x, acc2[0][0]);
            acc2[0][1] = ffma2(a0, bv.y, acc2[0][1]);
            acc2[1][0] = ffma2(a1, bv.x, acc2[1][0]);
            acc2[1][1] = ffma2(a1, bv.y, acc2[1][1]);
            acc2[2][0] = ffma2(a2, bv.x, acc2[2][0]);
            acc2[2][1] = ffma2(a2, bv.y, acc2[2][1]);
            acc2[3][0] = ffma2(a3, bv.x, acc2[3][0]);
            acc2[3][1] = ffma2(a3, bv.y, acc2[3][1]);
        }
        __syncthreads();
    }
    float* pf = (float*)g_pf;
    #pragma unroll
    for(int ii=0;ii<4;ii++){
        int h = h0 + r0 + ii;
        float a0,a1,a2,a3;
        unpack2(acc2[ii][0], a0, a1);
        unpack2(acc2[ii][1], a2, a3);
        float vals[4] = {a0,a1,a2,a3};
        #pragma unroll
        for(int jj=0;jj<4;jj++){
            int col = col0 + c0 + jj;
            int n = col & 1023, comp = col >> 10;
            pf[(((b*CD)+h)*NN + n)*4 + comp] = vals[jj];
        }
    }
}

// ---------------- 9: final d = wcd @ cat ----------------
__global__ void k_dvec(const float* __restrict__ wcd){
    int i = blockIdx.x*256 + threadIdx.x;   // B*3072
    int b = i/3072, col = i - b*3072;
    const float* catb = g_cat + b*CATSTR;
    float s = 0.f;
    for(int c=0;c<CATC;c++) s = fmaf(wcd[c], catb[c*3072 + col], s);
    int n = col & 1023, comp = col >> 10;
    ((float*)g_df)[(b*NN+n)*4 + comp] = s;
}

// ---------------- 10: final BN stats (nm-form, double per element) ----------------
__global__ void k_fstats(const float* __restrict__ bw, const float* __restrict__ bb){
    int h = blockIdx.x, t = threadIdx.x;    // 256 threads
    double s1=0.0, s2=0.0;
    for(int i=t; i<BB*NN; i+=256){
        int b = i>>10, n = i&1023;
        float4 p = g_pf[((b*CD)+h)*NN + n];
        float ss = p.x*p.x + p.y*p.y + p.z*p.z;
        float nm = sqrtf(ss) + 1e-6f;
        double nd = (double)nm;
        s1 += nd; s2 += nd*nd;
    }
    __shared__ double sh1[8], sh2[8];
    s1 = warpSumD(s1); s2 = warpSumD(s2);
    if((t&31)==0){ sh1[t>>5]=s1; sh2[t>>5]=s2; }
    __syncthreads();
    if(t==0){
        double S1=0.0, S2=0.0;
        #pragma unroll
        for(int u=0;u<8;u++){ S1+=sh1[u]; S2+=sh2[u]; }
        const double invc = 1.0/(double)(BB*NN);
        double m = S1*invc;
        double var = S2*invc - m*m;
        double istd = 1.0/sqrt(var + 1e-5);
        float A = (float)(istd*(double)bw[h]);
        g_bnA[h] = A;
        g_bnB[h] = (float)((double)bb[h] - m*(double)A);
    }
}

// ---------------- 11: finalize — BN + leaky + mean over N ----------------
__global__ void k_final(float* __restrict__ out){
    int h = blockIdx.x, b = blockIdx.y;
    float A = g_bnA[h], Bc = g_bnB[h];
    float ox=0.f, oy=0.f, oz=0.f;
    for(int n=threadIdx.x; n<NN; n+=256){
        float4 p = g_pf[((b*CD)+h)*NN + n];
        float4 d = g_df[b*NN + n];
        float ss = p.x*p.x + p.y*p.y + p.z*p.z;
        float nm = sqrtf(ss) + 1e-6f;
        float r = __fdividef(1.f, nm);
        float sc = A + Bc*r;
        float px = p.x*sc, py = p.y*sc, pz = p.z*sc;
        float dot = px*d.x + py*d.y + pz*d.z;
        if(dot < 0.f){
            float cc = 0.8f*dot*__fdividef(1.f, d.x*d.x + d.y*d.y + d.z*d.z + 1e-6f);
            px -= cc*d.x; py -= cc*d.y; pz -= cc*d.z;
        }
        ox += px; oy += py; oz += pz;
    }
    __shared__ float sx[8], sy[8], sz[8];
    ox = warpSum(ox); oy = warpSum(oy); oz = warpSum(oz);
    int t = threadIdx.x;
    if((t&31)==0){ sx[t>>5]=ox; sy[t>>5]=oy; sz[t>>5]=oz; }
    __syncthreads();
    if(t==0){
        float X=0.f, Y=0.f, Z=0.f;
        #pragma unroll
        for(int u=0;u<8;u++){ X+=sx[u]; Y+=sy[u]; Z+=sz[u]; }
        const float s = 1.f/(float)NN;
        float* o = out + (b*CD + h)*3;
        o[0] = X*s; o[1] = Y*s; o[2] = Z*s;
    }
}

// ---------------- host orchestration ----------------
static void conv_layer(const float* in, int C, int bstr,
                       const float* wf, const float* wd,
                       const float* bnw, const float* bnb, int c0_out){
    int D = C*3;
    k_dist<<<dim3(16,16,BB), 256>>>(in, D, bstr);
    k_topk<<<BB*NN/8, 256>>>();
    k_yq  <<<dim3(NN/32, 2, BB), 192>>>(in, C, bstr, wf, wd);
    k_statsA<<<dim3(NN/4, BB), 256>>>();
    k_statsR<<<HH, 256>>>(bnw, bnb);
    k_passB<<<dim3(NN/4, BB), 256>>>(c0_out);
}

extern "C" void kernel_launch(void* const* d_in, const int* in_sizes, int n_in,
                              void* d_out, int out_size){
    const float* x    = (const float*)d_in[0];
    const float* w1f  = (const float*)d_in[1];
    const float* w1d  = (const float*)d_in[2];
    const float* bn1w = (const float*)d_in[3];
    const float* bn1b = (const float*)d_in[4];
    const float* w2f  = (const float*)d_in[5];
    const float* w2d  = (const float*)d_in[6];
    const float* bn2w = (const float*)d_in[7];
    const float* bn2b = (const float*)d_in[8];
    const float* w3f  = (const float*)d_in[9];
    const float* w3d  = (const float*)d_in[10];
    const float* bn3w = (const float*)d_in[11];
    const float* bn3b = (const float*)d_in[12];
    const float* w4f  = (const float*)d_in[13];
    const float* w4d  = (const float*)d_in[14];
    const float* bn4w = (const float*)d_in[15];
    const float* bn4b = (const float*)d_in[16];
    const float* wcf  = (const float*)d_in[17];
    const float* wcd  = (const float*)d_in[18];
    const float* bncw = (const float*)d_in[19];
    const float* bncb = (const float*)d_in[20];
    float* out = (float*)d_out;

    float *pts = nullptr, *cat = nullptr;
    cudaGetSymbolAddress((void**)&pts, g_pts);
    cudaGetSymbolAddress((void**)&cat, g_cat);

    k_transpose<<<32, 256>>>(x);

    conv_layer(pts, 1, 3*NN, w1f, w1d, bn1w, bn1b, 0);
    conv_layer(cat,            HH, CATSTR, w2f, w2d, bn2w, bn2b, HH);
    conv_layer(cat + HH*3*NN,  HH, CATSTR, w3f, w3d, bn3w, bn3b, 2*HH);
    conv_layer(cat + 2*HH*3*NN,HH, CATSTR, w4f, w4d, bn4w, bn4b, 3*HH);

    k_pgemm <<<dim3(3072/64, CD/64, BB), 256>>>(wcf);
    k_dvec  <<<BB*3072/256, 256>>>(wcd);
    k_fstats<<<CD, 256>>>(bncw, bncb);
    k_final <<<dim3(CD, BB), 256>>>(out);
}

// round 17
// speedup vs baseline: 1.1598x; 1.0823x over previous
#include <cuda_runtime.h>
#include <math.h>

#define BB 8
#define NN 1024
#define KK 20
#define HH 64
#define CD 128
#define CATC 256
#define CATSTR (CATC*3*NN)
#define NBLK 2048   // statsA partial blocks = (NN/4)*BB

typedef unsigned long long u64;

// ---------------- scratch ----------------
__device__ float  g_pts[BB*3*NN];
__device__ float  g_cat[BB*CATC*3*NN];
__device__ float  g_dist[BB*NN*NN];
__device__ int    g_idx[BB*NN*KK];
// h-contiguous layout: [b][n][h] float4
__device__ float4 g_yf[BB*NN*HH];
__device__ float4 g_qf[BB*NN*HH];
__device__ float4 g_yd[BB*NN*HH];
__device__ float4 g_qd[BB*NN*HH];
__device__ double g_p1[NBLK*HH], g_p2[NBLK*HH];   // [blk][h] coalesced partials
__device__ float  g_bnA[CD], g_bnB[CD];
__device__ float4 g_pf[BB*CD*NN];
__device__ float4 g_df[BB*NN];

__device__ __forceinline__ float warpSum(float v){
    #pragma unroll
    for(int o=16;o;o>>=1) v += __shfl_down_sync(0xffffffffu, v, o);
    return v;
}
__device__ __forceinline__ double warpSumD(double v){
    #pragma unroll
    for(int o=16;o;o>>=1) v += __shfl_down_sync(0xffffffffu, v, o);
    return v;
}

// packed f32x2 helpers (sm_103a)
__device__ __forceinline__ u64 ffma2(u64 a, u64 b, u64 c){
    u64 d;
    asm("fma.rn.f32x2 %0, %1, %2, %3;" : "=l"(d) : "l"(a), "l"(b), "l"(c));
    return d;
}
__device__ __forceinline__ u64 pack2(float x){
    u64 d;
    asm("mov.b64 %0, {%1, %1};" : "=l"(d) : "f"(x));
    return d;
}
__device__ __forceinline__ void unpack2(u64 d, float& lo, float& hi){
    asm("mov.b64 {%0, %1}, %2;" : "=f"(lo), "=f"(hi) : "l"(d));
}

// monotonic uint key; -0.0 normalized so order matches float compare exactly
__device__ __forceinline__ unsigned fkey(float f){
    unsigned u = __float_as_uint(f);
    if(u == 0x80000000u) u = 0u;
    return (u & 0x80000000u) ? ~u : (u | 0x80000000u);
}

// ---------------- 0: transpose x[B,N,3] -> pts[B,3,N] ----------------
__global__ void k_transpose(const float* __restrict__ x){
    int i = blockIdx.x*256 + threadIdx.x;
    if(i < BB*NN){
        int b = i>>10, n = i&1023;
        const float* src = x + (size_t)(b*NN+n)*3;
        g_pts[(b*3+0)*NN+n] = src[0];
        g_pts[(b*3+1)*NN+n] = src[1];
        g_pts[(b*3+2)*NN+n] = src[2];
    }
}

// ---------------- 2: Gram + fused norms, f32x2, float4 staging ----------------
__global__ void k_dist(const float* __restrict__ in, int D, int bstr){
    int b = blockIdx.z, n0 = blockIdx.y*64, m0 = blockIdx.x*64;
    __shared__ __align__(16) float sA[16][64];
    __shared__ __align__(16) float sB[16][64];
    __shared__ float sxn[64], sxm[64];
    int t = threadIdx.x;
    int r0 = (t>>4)<<2, c0 = (t&15)<<2;
    u64 acc2[4][2];
    #pragma unroll
    for(int ii=0;ii<4;ii++){ acc2[ii][0]=0ull; acc2[ii][1]=0ull; }
    float rn = 0.f;
    const float* fb = in + b*bstr;
    int sdd = t>>4, si4 = (t&15)<<2;
    for(int d0=0; d0<D; d0+=16){
        int d = d0 + sdd;
        float4 va = make_float4(0.f,0.f,0.f,0.f), vb = va;
        if(d < D){
            va = *(const float4*)&fb[d*NN + n0 + si4];
            vb = *(const float4*)&fb[d*NN + m0 + si4];
        }
        *(float4*)&sA[sdd][si4] = va;
        *(float4*)&sB[sdd][si4] = vb;
        __syncthreads();
        if(t < 64){
            #pragma unroll
            for(int dd=0;dd<16;dd++){ float v = sA[dd][t]; rn = fmaf(v,v,rn); }
        } else if(t < 128){
            int c = t-64;
            #pragma unroll
            for(int dd=0;dd<16;dd++){ float v = sB[dd][c]; rn = fmaf(v,v,rn); }
        }
        #pragma unroll
        for(int dd=0; dd<16; dd++){
            float4 av = *(const float4*)&sA[dd][r0];
            ulonglong2 bv = *(const ulonglong2*)&sB[dd][c0];
            u64 a0 = pack2(av.x), a1 = pack2(av.y), a2 = pack2(av.z), a3 = pack2(av.w);
            acc2[0][0] = ffma2(a0, bv.x, acc2[0][0]);
            acc2[0][1] = ffma2(a0, bv.y, acc2[0][1]);
            acc2[1][0] = ffma2(a1, bv.x, acc2[1][0]);
            acc2[1][1] = ffma2(a1, bv.y, acc2[1][1]);
            acc2[2][0] = ffma2(a2, bv.x, acc2[2][0]);
            acc2[2][1] = ffma2(a2, bv.y, acc2[2][1]);
            acc2[3][0] = ffma2(a3, bv.x, acc2[3][0]);
            acc2[3][1] = ffma2(a3, bv.y, acc2[3][1]);
        }
        __syncthreads();
    }
    if(t < 64) sxn[t] = rn;
    else if(t < 128) sxm[t-64] = rn;
    __syncthreads();
    float xn[4], xm[4];
    #pragma unroll
    for(int ii=0;ii<4;ii++) xn[ii] = sxn[r0 + ii];
    #pragma unroll
    for(int jj=0;jj<4;jj++) xm[jj] = sxm[c0 + jj];
    #pragma unroll
    for(int ii=0;ii<4;ii++){
        int n = n0 + r0 + ii;
        float a0,a1,a2,a3;
        unpack2(acc2[ii][0], a0, a1);
        unpack2(acc2[ii][1], a2, a3);
        float4 o;
        o.x = 2.f*a0 - xn[ii] - xm[0];
        o.y = 2.f*a1 - xn[ii] - xm[1];
        o.z = 2.f*a2 - xn[ii] - xm[2];
        o.w = 2.f*a3 - xn[ii] - xm[3];
        *(float4*)&g_dist[(size_t)(b*NN+n)*NN + m0 + c0] = o;
    }
}

// 4-chain ILP local argmax over 32 register keys (ties -> smallest index)
__device__ __forceinline__ void scan32(const unsigned* kv, unsigned& lk, int& li){
    unsigned k0=kv[0];  int i0=0;
    unsigned k1=kv[8];  int i1=8;
    unsigned k2=kv[16]; int i2=16;
    unsigned k3=kv[24]; int i3=24;
    #pragma unroll
    for(int j=1;j<8;j++){
        if(kv[j]    > k0){ k0=kv[j];    i0=j;    }
        if(kv[8+j]  > k1){ k1=kv[8+j];  i1=8+j;  }
        if(kv[16+j] > k2){ k2=kv[16+j]; i2=16+j; }
        if(kv[24+j] > k3){ k3=kv[24+j]; i3=24+j; }
    }
    if(k1 > k0){ k0=k1; i0=i1; }
    if(k3 > k2){ k2=k3; i2=i3; }
    if(k2 > k0){ k0=k2; i0=i2; }
    lk=k0; li=i0;
}

// ---------------- 3: top-20 per row — warp per row, REDUX argmax ----------------
__global__ void k_topk(){
    int row = blockIdx.x*8 + (threadIdx.x>>5);
    int lane = threadIdx.x & 31;
    const float* dr = g_dist + (size_t)row*NN;
    unsigned kv[32];
    #pragma unroll
    for(int j=0;j<32;j++) kv[j] = fkey(dr[lane + (j<<5)]);   // coalesced
    unsigned lk; int li;
    scan32(kv, lk, li);
    int* outp = g_idx + row*KK;
    #pragma unroll 1
    for(int kk=0; kk<KK; kk++){
        unsigned m = __reduce_max_sync(0xffffffffu, lk);
        unsigned cand = (lk == m) ? (unsigned)(lane + (li<<5)) : 0xffffffffu;
        unsigned bidx = __reduce_min_sync(0xffffffffu, cand);
        if(lane == 0) outp[kk] = (int)bidx;
        if((bidx & 31u) == (unsigned)lane){
            #pragma unroll
            for(int j=0;j<32;j++) if(j==li) kv[j] = 0u;
            scan32(kv, lk, li);
        }
    }
}

// ---------------- 4: tiny GEMMs y/q = W @ x (f32x2), PAIR-MERGED ----------------
// grid (N/32, pair 0..1, B); block 192 = 64h x 3comp
__global__ void k_yq(const float* __restrict__ in, int C, int bstr,
                     const float* __restrict__ wf, const float* __restrict__ wd){
    int b = blockIdx.z, pair = blockIdx.y, n0 = blockIdx.x*32;
    __shared__ __align__(16) float xs[HH*3*32];
    __shared__ float os[3][HH][33];
    int t = threadIdx.x;                  // 192
    const float* xb = in + b*bstr;
    int R = C*3;
    for(int l=t; l<R*32; l+=192){
        int row = l>>5, col = l&31;
        xs[l] = xb[row*NN + n0 + col];
    }
    __syncthreads();
    int h = t/3, comp = t - h*3;
    const float* w = pair ? wd : wf;
    int twoC = 2*C;
    #pragma unroll 1
    for(int sub=0; sub<2; sub++){
        u64 acc[16];
        #pragma unroll
        for(int j=0;j<16;j++) acc[j]=0ull;
        for(int c=0;c<C;c++){
            float wv = w[h*twoC + c];
            if(sub) wv = w[h*twoC + C + c] - wv;
            u64 w2 = pack2(wv);
            const u64* xr = (const u64*)(xs + (c*3 + comp)*32);
            #pragma unroll
            for(int j=0;j<16;j++) acc[j] = ffma2(w2, xr[j], acc[j]);
        }
        #pragma unroll
        for(int j=0;j<16;j++){
            float f0,f1;
            unpack2(acc[j], f0, f1);
            os[comp][h][2*j]   = f0;
            os[comp][h][2*j+1] = f1;
        }
        __syncthreads();
        float4* outp = (pair==0 ? (sub==0 ? g_yf : g_qf)
                                : (sub==0 ? g_yd : g_qd))
                       + ((size_t)b*NN + n0)*HH;
        for(int idx=t; idx<HH*32; idx+=192){
            int n = idx>>6, h2 = idx&63;
            outp[(size_t)n*HH + h2] = make_float4(os[0][h2][n], os[1][h2][n], os[2][h2][n], 0.f);
        }
        __syncthreads();
    }
}

// ---------------- 5: pass A — BN stats; h-gathers; nm-form double; smem ix ----------------
// grid (NN/4, BB), block 256: t = nloc*64 + h
__global__ void k_statsA(){
    int b = blockIdx.y, t = threadIdx.x;
    int h = t & 63, nloc = t >> 6;
    int n = blockIdx.x*4 + nloc;
    __shared__ int six[4][KK];
    if(t < 4*KK){
        int nl = t/KK, k = t - nl*KK;
        six[nl][k] = g_idx[(b*NN + blockIdx.x*4 + nl)*KK + k];
    }
    const float4* yf = g_yf + (size_t)b*NN*HH;
    float4 q = g_qf[((size_t)b*NN + n)*HH + h];
    __syncthreads();
    double s1 = 0.0, s2 = 0.0;
    #pragma unroll
    for(int k=0;k<KK;k++){
        int m = six[nloc][k];
        float4 y = yf[(size_t)m*HH + h];
        float px = y.x+q.x, py = y.y+q.y, pz = y.z+q.z;
        float ss = px*px + py*py + pz*pz;
        float nm = sqrtf(ss) + 1e-6f;        // exact reference norm
        double nd = (double)nm;
        s1 += nd; s2 += nd*nd;               // nm-form (frozen; eps-algebra banned)
    }
    __shared__ double sr[256], ssd[256];
    sr[t] = s1; ssd[t] = s2;
    __syncthreads();
    if(t < 64){
        double S1 = sr[t] + sr[t+64] + sr[t+128] + sr[t+192];
        double S2 = ssd[t] + ssd[t+64] + ssd[t+128] + ssd[t+192];
        int blk = b*(NN/4) + blockIdx.x;     // 0..NBLK-1
        g_p1[blk*64 + t] = S1;               // coalesced
        g_p2[blk*64 + t] = S2;
    }
}

// ---------------- 6: reduce partials -> folded BN coeffs (plain fp64) ----------------
__global__ void k_statsR(const float* __restrict__ bnw, const float* __restrict__ bnb){
    int h = blockIdx.x, t = threadIdx.x;   // 256 threads
    double s1=0.0, s2=0.0;
    for(int i=t; i<NBLK; i+=256){ s1 += g_p1[i*64+h]; s2 += g_p2[i*64+h]; }
    s1 = warpSumD(s1); s2 = warpSumD(s2);
    __shared__ double a1[8], a2[8];
    if((t&31)==0){ a1[t>>5]=s1; a2[t>>5]=s2; }
    __syncthreads();
    if(t==0){
        double S1=0.0, S2=0.0;
        #pragma unroll
        for(int u=0;u<8;u++){ S1+=a1[u]; S2+=a2[u]; }
        const double invc = 1.0/(double)(BB*NN*KK);
        double m = S1*invc;
        double var = S2*invc - m*m;
        double istd = 1.0/sqrt(var + 1e-5);
        float A = (float)(istd * (double)bnw[h]);
        g_bnA[h] = A;
        g_bnB[h] = (float)((double)bnb[h] - m*(double)A);
    }
}

// ---------------- 7: pass B — h-gathers; BN + dir-LeakyReLU + mean over k; smem ix ----------------
// grid (NN/4, BB), block 256: t = nloc*64 + h
__global__ void k_passB(int c0){
    int b = blockIdx.y, t = threadIdx.x;
    int h = t & 63;
    int nloc = t >> 6;
    int n = blockIdx.x*4 + nloc;
    __shared__ int six[4][KK];
    if(t < 4*KK){
        int nl = t/KK, k = t - nl*KK;
        six[nl][k] = g_idx[(b*NN + blockIdx.x*4 + nl)*KK + k];
    }
    size_t base = (size_t)b*NN*HH;
    float4 q  = g_qf[base + (size_t)n*HH + h];
    float4 qd = g_qd[base + (size_t)n*HH + h];
    float A = g_bnA[h], Bc = g_bnB[h];
    __syncthreads();
    float ox=0.f, oy=0.f, oz=0.f;
    #pragma unroll 5
    for(int k=0;k<KK;k++){
        int m = six[nloc][k];
        float4 y  = g_yf[base + (size_t)m*HH + h];
        float4 yD = g_yd[base + (size_t)m*HH + h];
        float px = y.x+q.x, py = y.y+q.y, pz = y.z+q.z;
        float dx = yD.x+qd.x, dy = yD.y+qd.y, dz = yD.z+qd.z;
        float ss = px*px + py*py + pz*pz;
        float nm = sqrtf(ss) + 1e-6f;
        float inv = __fdividef(1.f, nm);
        float sc = A + Bc*inv;
        px *= sc; py *= sc; pz *= sc;
        float dot = px*dx + py*dy + pz*dz;
        if(dot < 0.f){
            float cc = 0.8f*dot*__fdividef(1.f, dx*dx + dy*dy + dz*dz + 1e-6f);
            px -= cc*dx; py -= cc*dy; pz -= cc*dz;
        }
        ox += px; oy += py; oz += pz;
    }
    const float s = 1.f/(float)KK;
    int obase = b*CATSTR + (c0+h)*3*NN + n;
    g_cat[obase]        = ox*s;
    g_cat[obase+NN]     = oy*s;
    g_cat[obase+2*NN]   = oz*s;
}

// ---------------- 8: final p = wcf @ cat (f32x2) ----------------
__global__ void k_pgemm(const float* __restrict__ wcf){
    int b = blockIdx.z, h0 = blockIdx.y*64, col0 = blockIdx.x*64;
    __shared__ __align__(16) float sW[16][68];
    __shared__ __align__(16) float sX[16][64];
    int t = threadIdx.x;
    int r0 = (t>>4)<<2, c0 = (t&15)<<2;
    u64 acc2[4][2];
    #pragma unroll
    for(int ii=0;ii<4;ii++){ acc2[ii][0]=0ull; acc2[ii][1]=0ull; }
    const float* catb = g_cat + b*CATSTR;
    for(int cb=0; cb<CATC; cb+=16){
        for(int l=t; l<1024; l+=256){
            int i = l>>4, cc = l&15;
            sW[cc][i] = wcf[(h0+i)*CATC + cb + cc];
        }
        for(int l=t; l<1024; l+=256){
            int cc = l>>6, j = l&63;
            sX[cc][j] = catb[(cb+cc)*3072 + col0 + j];
        }
        __syncthreads();
        #pragma unroll
        for(int cc=0; cc<16; cc++){
            float4 av = *(const float4*)&sW[cc][r0];
            ulonglong2 bv = *(const ulonglong2*)&sX[cc][c0];
            u64 a0 = pack2(av.x), a1 = pack2(av.y), a2 = pack2(av.z), a3 = pack2(av.w);
            acc2[0][0] = ffma2(a0, bv.x, acc2[0][0]);
            acc2[0][1] = ffma2(a0, bv.y, acc2[0][1]);
            acc2[1][0] = ffma2(a1, bv.x, acc2[1][0]);
            acc2[1][1] = ffma2(a1, bv.y, acc2[1][1]);
            acc2[2][0] = ffma2(a2, bv.x, acc2[2][0]);
            acc2[2][1] = ffma2(a2, bv.y, acc2[2][1]);
            acc2[3][0] = ffma2(a3, bv.x, acc2[3][0]);
            acc2[3][1] = ffma2(a3, bv.y, acc2[3][1]);
        }
        __syncthreads();
    }
    float* pf = (float*)g_pf;
    #pragma unroll
    for(int ii=0;ii<4;ii++){
        int h = h0 + r0 + ii;
        float a0,a1,a2,a3;
        unpack2(acc2[ii][0], a0, a1);
        unpack2(acc2[ii][1], a2, a3);
        float vals[4] = {a0,a1,a2,a3};
        #pragma unroll
        for(int jj=0;jj<4;jj++){
            int col = col0 + c0 + jj;
            int n = col & 1023, comp = col >> 10;
            pf[(((b*CD)+h)*NN + n)*4 + comp] = vals[jj];
        }
    }
}

// ---------------- 9: final d = wcd @ cat ----------------
__global__ void k_dvec(const float* __restrict__ wcd){
    int i = blockIdx.x*256 + threadIdx.x;   // B*3072
    int b = i/3072, col = i - b*3072;
    const float* catb = g_cat + b*CATSTR;
    float s = 0.f;
    for(int c=0;c<CATC;c++) s = fmaf(wcd[c], catb[c*3072 + col], s);
    int n = col & 1023, comp = col >> 10;
    ((float*)g_df)[(b*NN+n)*4 + comp] = s;
}

// ---------------- 10: final BN stats (nm-form, double per element) ----------------
__global__ void k_fstats(const float* __restrict__ bw, const float* __restrict__ bb){
    int h = blockIdx.x, t = threadIdx.x;    // 256 threads
    double s1=0.0, s2=0.0;
    for(int i=t; i<BB*NN; i+=256){
        int b = i>>10, n = i&1023;
        float4 p = g_pf[((b*CD)+h)*NN + n];
        float ss = p.x*p.x + p.y*p.y + p.z*p.z;
        float nm = sqrtf(ss) + 1e-6f;
        double nd = (double)nm;
        s1 += nd; s2 += nd*nd;
    }
    __shared__ double sh1[8], sh2[8];
    s1 = warpSumD(s1); s2 = warpSumD(s2);
    if((t&31)==0){ sh1[t>>5]=s1; sh2[t>>5]=s2; }
    __syncthreads();
    if(t==0){
        double S1=0.0, S2=0.0;
        #pragma unroll
        for(int u=0;u<8;u++){ S1+=sh1[u]; S2+=sh2[u]; }
        const double invc = 1.0/(double)(BB*NN);
        double m = S1*invc;
        double var = S2*invc - m*m;
        double istd = 1.0/sqrt(var + 1e-5);
        float A = (float)(istd*(double)bw[h]);
        g_bnA[h] = A;
        g_bnB[h] = (float)((double)bb[h] - m*(double)A);
    }
}

// ---------------- 11: finalize — BN + leaky + mean over N ----------------
__global__ void k_final(float* __restrict__ out){
    int h = blockIdx.x, b = blockIdx.y;
    float A = g_bnA[h], Bc = g_bnB[h];
    float ox=0.f, oy=0.f, oz=0.f;
    for(int n=threadIdx.x; n<NN; n+=256){
        float4 p = g_pf[((b*CD)+h)*NN + n];
        float4 d = g_df[b*NN + n];
        float ss = p.x*p.x + p.y*p.y + p.z*p.z;
        float nm = sqrtf(ss) + 1e-6f;
        float r = __fdividef(1.f, nm);
        float sc = A + Bc*r;
        float px = p.x*sc, py = p.y*sc, pz = p.z*sc;
        float dot = px*d.x + py*d.y + pz*d.z;
        if(dot < 0.f){
            float cc = 0.8f*dot*__fdividef(1.f, d.x*d.x + d.y*d.y + d.z*d.z + 1e-6f);
            px -= cc*d.x; py -= cc*d.y; pz -= cc*d.z;
        }
        ox += px; oy += py; oz += pz;
    }
    __shared__ float sx[8], sy[8], sz[8];
    ox = warpSum(ox); oy = warpSum(oy); oz = warpSum(oz);
    int t = threadIdx.x;
    if((t&31)==0){ sx[t>>5]=ox; sy[t>>5]=oy; sz[t>>5]=oz; }
    __syncthreads();
    if(t==0){
        float X=0.f, Y=0.f, Z=0.f;
        #pragma unroll
        for(int u=0;u<8;u++){ X+=sx[u]; Y+=sy[u]; Z+=sz[u]; }
        const float s = 1.f/(float)NN;
        float* o = out + (b*CD + h)*3;
        o[0] = X*s; o[1] = Y*s; o[2] = Z*s;
    }
}

// ---------------- host orchestration (two-stream overlap) ----------------
struct Aux {
    cudaStream_t s2;
    cudaEvent_t fork, join;
    Aux(){
        cudaStreamCreateWithFlags(&s2, cudaStreamNonBlocking);
        cudaEventCreateWithFlags(&fork, cudaEventDisableTiming);
        cudaEventCreateWithFlags(&join, cudaEventDisableTiming);
    }
};
static Aux& aux(){ static Aux a; return a; }

static void conv_layer(const float* in, int C, int bstr,
                       const float* wf, const float* wd,
                       const float* bnw, const float* bnb, int c0_out){
    int D = C*3;
    Aux& a = aux();
    // fork: yq on s2, dist+topk on main; join before statsA
    cudaEventRecord(a.fork, 0);
    cudaStreamWaitEvent(a.s2, a.fork, 0);
    k_yq<<<dim3(NN/32, 2, BB), 192, 0, a.s2>>>(in, C, bstr, wf, wd);
    cudaEventRecord(a.join, a.s2);
    k_dist<<<dim3(16,16,BB), 256>>>(in, D, bstr);
    k_topk<<<BB*NN/8, 256>>>();
    cudaStreamWaitEvent(0, a.join, 0);
    k_statsA<<<dim3(NN/4, BB), 256>>>();
    k_statsR<<<HH, 256>>>(bnw, bnb);
    k_passB<<<dim3(NN/4, BB), 256>>>(c0_out);
}

extern "C" void kernel_launch(void* const* d_in, const int* in_sizes, int n_in,
                              void* d_out, int out_size){
    const float* x    = (const float*)d_in[0];
    const float* w1f  = (const float*)d_in[1];
    const float* w1d  = (const float*)d_in[2];
    const float* bn1w = (const float*)d_in[3];
    const float* bn1b = (const float*)d_in[4];
    const float* w2f  = (const float*)d_in[5];
    const float* w2d  = (const float*)d_in[6];
    const float* bn2w = (const float*)d_in[7];
    const float* bn2b = (const float*)d_in[8];
    const float* w3f  = (const float*)d_in[9];
    const float* w3d  = (const float*)d_in[10];
    const float* bn3w = (const float*)d_in[11];
    const float* bn3b = (const float*)d_in[12];
    const float* w4f  = (const float*)d_in[13];
    const float* w4d  = (const float*)d_in[14];
    const float* bn4w = (const float*)d_in[15];
    const float* bn4b = (const float*)d_in[16];
    const float* wcf  = (const float*)d_in[17];
    const float* wcd  = (const float*)d_in[18];
    const float* bncw = (const float*)d_in[19];
    const float* bncb = (const float*)d_in[20];
    float* out = (float*)d_out;

    float *pts = nullptr, *cat = nullptr;
    cudaGetSymbolAddress((void**)&pts, g_pts);
    cudaGetSymbolAddress((void**)&cat, g_cat);

    Aux& a = aux();

    k_transpose<<<32, 256>>>(x);

    conv_layer(pts, 1, 3*NN, w1f, w1d, bn1w, bn1b, 0);
    conv_layer(cat,            HH, CATSTR, w2f, w2d, bn2w, bn2b, HH);
    conv_layer(cat + HH*3*NN,  HH, CATSTR, w3f, w3d, bn3w, bn3b, 2*HH);
    conv_layer(cat + 2*HH*3*NN,HH, CATSTR, w4f, w4d, bn4w, bn4b, 3*HH);

    // epilogue: dvec on s2 || pgemm+fstats on main; join before k_final
    cudaEventRecord(a.fork, 0);
    cudaStreamWaitEvent(a.s2, a.fork, 0);
    k_dvec<<<BB*3072/256, 256, 0, a.s2>>>(wcd);
    cudaEventRecord(a.join, a.s2);
    k_pgemm <<<dim3(3072/64, CD/64, BB), 256>>>(wcf);
    k_fstats<<<CD, 256>>>(bncw, bncb);
    cudaStreamWaitEvent(0, a.join, 0);
    k_final <<<dim3(CD, BB), 256>>>(out);
}